// round 8
// baseline (speedup 1.0000x reference)
#include <cuda_runtime.h>
#include <cstdint>

// ---------------------------------------------------------------------------
// SelectiveSSM on GB300 (base sm_103 target => mma.sync path).
// R8: GEMM CTA tile 256x128, warp tile 64x64 (4x2 warp grid), 1 CTA/SM.
// Fragment-major global operands (tf32-rounded, pre-permuted) staged with
// cp.async 16B identity copies. Prep/conv/combine identical to passing R7.
// ---------------------------------------------------------------------------

#define D_STATE 16
#define BSZ     2
#define LSEQ    4096
#define DMODEL  1024
#define DINNER  2048
#define NROWS   (BSZ * LSEQ)            // 8192
#define NXZ     (2 * DINNER)            // 4096
#define NPROJ   (2 * D_STATE + DINNER)  // 2080
#define NPROJ_PAD 2176                  // 17 * 128

// Scratch (device globals: allocation-free)
__device__ float g_xz[NROWS * (size_t)NXZ];        // GEMM1 out (normal layout)
__device__ float g_proj[NROWS * (size_t)NPROJ];    // GEMM2 out (normal layout)
// fragment-major operands
__device__ float g_xf[NROWS * (size_t)DMODEL];         // x        (A, GEMM1)
__device__ float g_winf[NXZ * (size_t)DMODEL];         // W_in     (B, GEMM1)
__device__ float g_xcf[NROWS * (size_t)DINNER];        // xc       (A, GEMM2)
__device__ float g_wxpf[NPROJ_PAD * (size_t)DINNER];   // W_xproj  (B, GEMM2, padded)
__device__ float g_yf[NROWS * (size_t)DINNER];         // y        (A, GEMM3)
__device__ float g_woutf[DMODEL * (size_t)DINNER];     // W_out    (B, GEMM3)

// ---------------------------------------------------------------------------
// Fragment layout (per 128x32 tile: 4096 u32) — identical to R5/R7.
//   A: [kstep(4)][mtile(8)][lane(32)][4 regs]
//   B: [kstep(4)][ntile(16)][lane(32)][2 regs]
// ---------------------------------------------------------------------------
__device__ __forceinline__ int aidx(int row, int k) {
    int kstep = k >> 3, kin = k & 7;
    int mtile = row >> 4, r = row & 15;
    int ln  = ((r & 7) << 2) | (kin & 3);
    int reg = ((kin >> 2) << 1) | (r >> 3);
    return ((((kstep << 3) + mtile) << 5) + ln) * 4 + reg;
}
__device__ __forceinline__ int bidx(int row, int k) {
    int kstep = k >> 3, kin = k & 7;
    int ntile = row >> 3, nin = row & 7;
    int ln  = (nin << 2) | (kin & 3);
    int reg = kin >> 2;
    return ((((kstep << 4) + ntile) << 5) + ln) * 2 + reg;
}

// RNA round-to-tf32 on raw bits (== cvt.rna.tf32.f32; container stays f32).
__device__ __forceinline__ uint32_t rtf32(float f) {
    return (__float_as_uint(f) + 0x1000u) & 0xFFFFE000u;
}

__device__ __forceinline__ void mma8(float acc[4], const uint32_t a[4], const uint32_t b[2]) {
    asm volatile(
        "mma.sync.aligned.m16n8k8.row.col.f32.tf32.tf32.f32 "
        "{%0,%1,%2,%3}, {%4,%5,%6,%7}, {%8,%9}, {%0,%1,%2,%3};"
        : "+f"(acc[0]), "+f"(acc[1]), "+f"(acc[2]), "+f"(acc[3])
        : "r"(a[0]), "r"(a[1]), "r"(a[2]), "r"(a[3]), "r"(b[0]), "r"(b[1]));
}

#define CP_ASYNC16(dst_u32, src_ptr) \
    asm volatile("cp.async.cg.shared.global [%0], [%1], 16;" \
                 :: "r"(dst_u32), "l"(src_ptr) : "memory")
#define CP_COMMIT() asm volatile("cp.async.commit_group;" ::: "memory")
#define CP_WAIT0()  asm volatile("cp.async.wait_group 0;" ::: "memory")

__device__ __forceinline__ uint32_t smem_u32a(const void* p) {
    uint32_t a;
    asm("{ .reg .u64 t; cvta.to.shared.u64 t, %1; cvt.u32.u64 %0, t; }"
        : "=r"(a) : "l"(p));
    return a;
}

// ---------------------------------------------------------------------------
// GEMM: C[M,N] = A[M,K] * B[N,K]^T, fragment-major operands.
// CTA tile 256x128, BK=32, 256 threads, warp grid 4(m) x 2(n), warp 64x64.
// smem per buffer: A0 16KB + A1 16KB + B 16KB = 48 KB; double buffered 96 KB.
// ---------------------------------------------------------------------------
#define GBUF_U32 12288           // 48 KB in u32
#define GSMEM    (2 * 49152)

__global__ void __launch_bounds__(256, 1)
gemm_frag(const float* __restrict__ Af, const float* __restrict__ Bf,
          float* __restrict__ C, int M, int N, int KT /* = K/32 */)
{
    extern __shared__ uint32_t smem[];
    const int tid  = threadIdx.x;
    const int lane = tid & 31;
    const int warp = tid >> 5;
    const int wm   = warp >> 1;       // 0..3
    const int wn   = warp & 1;        // 0..1
    const int m0   = blockIdx.y * 256;
    const int n0   = blockIdx.x * 128;

    const uint32_t sb = smem_u32a(smem);
    const float* At0 = Af + ((size_t)(2 * blockIdx.y) * KT) * 4096;
    const float* At1 = At0 + (size_t)KT * 4096;
    const float* Bt  = Bf + ((size_t)blockIdx.x * KT) * 4096;

    float acc[4][8][4];
#pragma unroll
    for (int i = 0; i < 4; i++)
#pragma unroll
        for (int j = 0; j < 8; j++)
#pragma unroll
            for (int q = 0; q < 4; q++) acc[i][j][q] = 0.f;

    // ---- prologue: stage tile 0 into buffer 0
#pragma unroll
    for (int i = 0; i < 4; i++) {
        const int slot = tid + 256 * i;                 // float4 slot (0..1023)
        CP_ASYNC16(sb + (uint32_t)slot * 16,           At0 + (size_t)slot * 4);
        CP_ASYNC16(sb + 16384u + (uint32_t)slot * 16,  At1 + (size_t)slot * 4);
        CP_ASYNC16(sb + 32768u + (uint32_t)slot * 16,  Bt  + (size_t)slot * 4);
    }
    CP_COMMIT();

    for (int kt = 0; kt < KT; ++kt) {
        CP_WAIT0();
        __syncthreads();

        // stage next tile into the other buffer (overlaps compute below)
        if (kt + 1 < KT) {
            const uint32_t boff = ((kt + 1) & 1) ? (GBUF_U32 * 4u) : 0u;  // bytes
            const float* An0 = At0 + (size_t)(kt + 1) * 4096;
            const float* An1 = At1 + (size_t)(kt + 1) * 4096;
            const float* Bn  = Bt  + (size_t)(kt + 1) * 4096;
#pragma unroll
            for (int i = 0; i < 4; i++) {
                const int slot = tid + 256 * i;
                CP_ASYNC16(sb + boff + (uint32_t)slot * 16,          An0 + (size_t)slot * 4);
                CP_ASYNC16(sb + boff + 16384u + (uint32_t)slot * 16, An1 + (size_t)slot * 4);
                CP_ASYNC16(sb + boff + 32768u + (uint32_t)slot * 16, Bn  + (size_t)slot * 4);
            }
            CP_COMMIT();
        }

        // ---- compute from buffer kt&1
        const uint32_t* Ab = smem + (kt & 1) * GBUF_U32 + (wm >> 1) * 4096;
        const uint32_t* Bb = smem + (kt & 1) * GBUF_U32 + 8192;
#pragma unroll
        for (int ks = 0; ks < 4; ++ks) {
            uint32_t af[4][4];
            uint32_t bf[8][2];
#pragma unroll
            for (int im = 0; im < 4; ++im) {
                const int mt = (wm & 1) * 4 + im;
                const uint4 t = *reinterpret_cast<const uint4*>(
                    &Ab[((((ks << 3) + mt) << 5) + lane) * 4]);
                af[im][0] = t.x; af[im][1] = t.y; af[im][2] = t.z; af[im][3] = t.w;
            }
#pragma unroll
            for (int jn = 0; jn < 8; ++jn) {
                const int nt = wn * 8 + jn;
                const uint2 t = *reinterpret_cast<const uint2*>(
                    &Bb[((((ks << 4) + nt) << 5) + lane) * 2]);
                bf[jn][0] = t.x; bf[jn][1] = t.y;
            }
#pragma unroll
            for (int im = 0; im < 4; ++im)
#pragma unroll
                for (int jn = 0; jn < 8; ++jn)
                    mma8(acc[im][jn], af[im], bf[jn]);
        }
    }

    // ---- epilogue
    const int g = lane >> 2, t = lane & 3;
#pragma unroll
    for (int im = 0; im < 4; ++im) {
        const int mrow = m0 + wm * 64 + im * 16 + g;
#pragma unroll
        for (int jn = 0; jn < 8; ++jn) {
            const int nb = n0 + wn * 64 + jn * 8;
            if (nb < N) {   // N % 8 == 0 always
                float2 v0 = make_float2(acc[im][jn][0], acc[im][jn][1]);
                float2 v1 = make_float2(acc[im][jn][2], acc[im][jn][3]);
                *reinterpret_cast<float2*>(&C[(size_t)mrow * N + nb + 2 * t])       = v0;
                *reinterpret_cast<float2*>(&C[(size_t)(mrow + 8) * N + nb + 2 * t]) = v1;
            }
        }
    }
}

// ---------------------------------------------------------------------------
// Prep: round to tf32 + permute into fragment-major layout (unchanged)
// ---------------------------------------------------------------------------
__global__ void __launch_bounds__(256)
prep_frag_a(const float* __restrict__ src, float* __restrict__ dst, int M, int K)
{
    const int idx = blockIdx.x * blockDim.x + threadIdx.x;
    const int kp = K >> 2;
    const int r  = idx / kp;
    const int kq = (idx - r * kp) << 2;
    if (r >= M) return;
    const float4 v = *reinterpret_cast<const float4*>(&src[(size_t)r * K + kq]);
    uint32_t* d = reinterpret_cast<uint32_t*>(dst) +
                  ((size_t)((r >> 7) * (K >> 5) + (kq >> 5))) * 4096;
    const int rr = r & 127, kk = kq & 31;
    d[aidx(rr, kk + 0)] = rtf32(v.x);
    d[aidx(rr, kk + 1)] = rtf32(v.y);
    d[aidx(rr, kk + 2)] = rtf32(v.z);
    d[aidx(rr, kk + 3)] = rtf32(v.w);
}

__global__ void __launch_bounds__(256)
prep_frag_b(const float* __restrict__ src, float* __restrict__ dst,
            int Nr, int K, int Npad)
{
    const int idx = blockIdx.x * blockDim.x + threadIdx.x;
    const int kp = K >> 2;
    const int r  = idx / kp;
    const int kq = (idx - r * kp) << 2;
    if (r >= Npad) return;
    float4 v = make_float4(0.f, 0.f, 0.f, 0.f);
    if (r < Nr) v = *reinterpret_cast<const float4*>(&src[(size_t)r * K + kq]);
    uint32_t* d = reinterpret_cast<uint32_t*>(dst) +
                  ((size_t)((r >> 7) * (K >> 5) + (kq >> 5))) * 4096;
    const int rr = r & 127, kk = kq & 31;
    d[bidx(rr, kk + 0)] = rtf32(v.x);
    d[bidx(rr, kk + 1)] = rtf32(v.y);
    d[bidx(rr, kk + 2)] = rtf32(v.z);
    d[bidx(rr, kk + 3)] = rtf32(v.w);
}

// ---------------------------------------------------------------------------
// Elementwise (unchanged from passing R7)
// ---------------------------------------------------------------------------
__device__ __forceinline__ float siluf(float v)     { return v / (1.f + expf(-v)); }
__device__ __forceinline__ float softplusf(float v) { return fmaxf(v, 0.f) + log1pf(expf(-fabsf(v))); }

// xc = tf32(silu(conv(xb))), fragment-A layout (feeds GEMM2)
__global__ void __launch_bounds__(256)
conv_silu_kernel(const float* __restrict__ xz, const float* __restrict__ cw,
                 const float* __restrict__ cb, float* __restrict__ xcf)
{
    const int idx = blockIdx.x * blockDim.x + threadIdx.x;
    const int c4 = (idx & 511) << 2;
    const int r  = idx >> 9;
    if (r >= NROWS) return;
    const int l = r & (LSEQ - 1);

    const float4 bias = *reinterpret_cast<const float4*>(&cb[c4]);
    float a0 = bias.x, a1 = bias.y, a2 = bias.z, a3 = bias.w;

#pragma unroll
    for (int k = 0; k < 4; k++) {
        const int ls = l + k - 3;
        if (ls >= 0) {
            const float4 v = *reinterpret_cast<const float4*>(
                &xz[(size_t)(r + k - 3) * NXZ + c4]);
            a0 = fmaf(__ldg(&cw[(c4 + 0) * 4 + k]), v.x, a0);
            a1 = fmaf(__ldg(&cw[(c4 + 1) * 4 + k]), v.y, a1);
            a2 = fmaf(__ldg(&cw[(c4 + 2) * 4 + k]), v.z, a2);
            a3 = fmaf(__ldg(&cw[(c4 + 3) * 4 + k]), v.w, a3);
        }
    }
    uint32_t* d = reinterpret_cast<uint32_t*>(xcf);
    const size_t base = ((size_t)((r >> 7) * (DINNER >> 5) + (c4 >> 5))) * 4096;
    const int rr = r & 127, kk = c4 & 31;
    d[base + aidx(rr, kk + 0)] = rtf32(siluf(a0));
    d[base + aidx(rr, kk + 1)] = rtf32(siluf(a1));
    d[base + aidx(rr, kk + 2)] = rtf32(siluf(a2));
    d[base + aidx(rr, kk + 3)] = rtf32(siluf(a3));
}

// y = tf32((softplus(dproj)*bc + D) * xc * silu(z)), fragment-A layout
__global__ void __launch_bounds__(128)
combine_kernel(const float* __restrict__ xz, const float* __restrict__ xcf,
               const float* __restrict__ proj, const float* __restrict__ D,
               float* __restrict__ yf)
{
    const int r   = blockIdx.x;
    const int tid = threadIdx.x;
    __shared__ float sbc;

    const float* prow = proj + (size_t)r * NPROJ;
    if (tid < 32) {
        float v = 0.f;
        if (tid < D_STATE) v = prow[tid] * prow[D_STATE + tid];
#pragma unroll
        for (int o = 8; o > 0; o >>= 1) v += __shfl_xor_sync(0xffffffffu, v, o);
        if (tid == 0) sbc = v;
    }
    __syncthreads();
    const float bc = sbc;

    const uint32_t* xcu = reinterpret_cast<const uint32_t*>(xcf);
    uint32_t*       yu  = reinterpret_cast<uint32_t*>(yf);
    const float*    zrow = xz + (size_t)r * NXZ + DINNER;
    const int rr = r & 127;
    const size_t rowbase = ((size_t)(r >> 7) * (DINNER >> 5)) * 4096;

#pragma unroll
    for (int i = 0; i < 4; i++) {
        const int c = (i * 128 + tid) * 4;
        const float4 dp = *reinterpret_cast<const float4*>(&prow[2 * D_STATE + c]);
        const float4 zv = *reinterpret_cast<const float4*>(&zrow[c]);
        const float4 Dv = *reinterpret_cast<const float4*>(&D[c]);
        const size_t base = rowbase + (size_t)(c >> 5) * 4096;
        const int kk = c & 31;
        const float x0 = __uint_as_float(xcu[base + aidx(rr, kk + 0)]);
        const float x1 = __uint_as_float(xcu[base + aidx(rr, kk + 1)]);
        const float x2 = __uint_as_float(xcu[base + aidx(rr, kk + 2)]);
        const float x3 = __uint_as_float(xcu[base + aidx(rr, kk + 3)]);
        yu[base + aidx(rr, kk + 0)] = rtf32((softplusf(dp.x) * bc + Dv.x) * x0 * siluf(zv.x));
        yu[base + aidx(rr, kk + 1)] = rtf32((softplusf(dp.y) * bc + Dv.y) * x1 * siluf(zv.y));
        yu[base + aidx(rr, kk + 2)] = rtf32((softplusf(dp.z) * bc + Dv.z) * x2 * siluf(zv.z));
        yu[base + aidx(rr, kk + 3)] = rtf32((softplusf(dp.w) * bc + Dv.w) * x3 * siluf(zv.w));
    }
}

// ---------------------------------------------------------------------------
// Launch
// ---------------------------------------------------------------------------
extern "C" void kernel_launch(void* const* d_in, const int* in_sizes, int n_in,
                              void* d_out, int out_size)
{
    const float* x      = (const float*)d_in[0];
    const float* W_in   = (const float*)d_in[1];
    const float* conv_w = (const float*)d_in[2];
    const float* conv_b = (const float*)d_in[3];
    const float* W_xp   = (const float*)d_in[4];
    const float* D      = (const float*)d_in[5];
    const float* W_out  = (const float*)d_in[6];
    float* out = (float*)d_out;

    void *p_xz, *p_proj, *p_xf, *p_winf, *p_xcf, *p_wxpf, *p_yf, *p_woutf;
    cudaGetSymbolAddress(&p_xz,    g_xz);
    cudaGetSymbolAddress(&p_proj,  g_proj);
    cudaGetSymbolAddress(&p_xf,    g_xf);
    cudaGetSymbolAddress(&p_winf,  g_winf);
    cudaGetSymbolAddress(&p_xcf,   g_xcf);
    cudaGetSymbolAddress(&p_wxpf,  g_wxpf);
    cudaGetSymbolAddress(&p_yf,    g_yf);
    cudaGetSymbolAddress(&p_woutf, g_woutf);

    cudaFuncSetAttribute(gemm_frag, cudaFuncAttributeMaxDynamicSharedMemorySize, GSMEM);

    // Prep: tf32-round + fragment-permute the GEMM operands
    prep_frag_a<<<(NROWS * (DMODEL / 4)) / 256, 256>>>(x, (float*)p_xf, NROWS, DMODEL);
    prep_frag_b<<<(NXZ * (DMODEL / 4)) / 256, 256>>>(W_in, (float*)p_winf, NXZ, DMODEL, NXZ);
    prep_frag_b<<<(NPROJ_PAD * (DINNER / 4)) / 256, 256>>>(W_xp, (float*)p_wxpf, NPROJ, DINNER, NPROJ_PAD);
    prep_frag_b<<<(DMODEL * (DINNER / 4)) / 256, 256>>>(W_out, (float*)p_woutf, DMODEL, DINNER, DMODEL);

    // GEMM1: xz = x @ W_in^T   (8192 x 4096 x 1024)
    gemm_frag<<<dim3(NXZ / 128, NROWS / 256), 256, GSMEM>>>(
        (const float*)p_xf, (const float*)p_winf, (float*)p_xz,
        NROWS, NXZ, DMODEL / 32);

    // conv + SiLU -> xc (fragment layout)
    conv_silu_kernel<<<(NROWS * 512) / 256, 256>>>(
        (const float*)p_xz, conv_w, conv_b, (float*)p_xcf);

    // GEMM2: proj = xc @ W_xproj^T  (8192 x 2080 x 2048), frag N padded to 2176
    gemm_frag<<<dim3(NPROJ_PAD / 128, NROWS / 256), 256, GSMEM>>>(
        (const float*)p_xcf, (const float*)p_wxpf, (float*)p_proj,
        NROWS, NPROJ, DINNER / 32);

    // combine -> y (fragment layout)
    combine_kernel<<<NROWS, 128>>>(
        (const float*)p_xz, (const float*)p_xcf, (const float*)p_proj, D, (float*)p_yf);

    // GEMM3: out = y @ W_out^T   (8192 x 1024 x 2048)
    gemm_frag<<<dim3(DMODEL / 128, NROWS / 256), 256, GSMEM>>>(
        (const float*)p_yf, (const float*)p_woutf, out,
        NROWS, DMODEL, DINNER / 32);
}

// round 9
// speedup vs baseline: 1.7492x; 1.7492x over previous
#include <cuda_runtime.h>
#include <cuda_fp16.h>
#include <cstdint>

// ---------------------------------------------------------------------------
// SelectiveSSM on GB300 (base sm_103 target => mma.sync path).
// R9: GEMMs switched tf32 -> fp16 (mma.sync.m16n8k16.f16, fp32 accumulate).
//   - same 10-bit mantissa as tf32 => identical rounding error profile
//   - 2x MACs per instruction, half the operand bytes end-to-end
// Architecture identical to passing R7: fragment-major global operands,
// identity cp.async staging, CTA 128x128, 2x4 warp grid, 2 CTA/SM.
// ---------------------------------------------------------------------------

#define D_STATE 16
#define BSZ     2
#define LSEQ    4096
#define DMODEL  1024
#define DINNER  2048
#define NROWS   (BSZ * LSEQ)            // 8192
#define NXZ     (2 * DINNER)            // 4096
#define NPROJ   (2 * D_STATE + DINNER)  // 2080
#define NPROJ_PAD 2176                  // 17 * 128

// Scratch (device globals: allocation-free)
__device__ float g_xz[NROWS * (size_t)NXZ];        // GEMM1 out (normal layout)
__device__ float g_proj[NROWS * (size_t)NPROJ];    // GEMM2 out (normal layout)
// fragment-major fp16 operands (u32 = packed half2)
__device__ uint32_t g_xf[NROWS * (size_t)DMODEL / 2];        // x       (A, GEMM1)
__device__ uint32_t g_winf[NXZ * (size_t)DMODEL / 2];        // W_in    (B, GEMM1)
__device__ uint32_t g_xcf[NROWS * (size_t)DINNER / 2];       // xc      (A, GEMM2)
__device__ uint32_t g_wxpf[NPROJ_PAD * (size_t)DINNER / 2];  // W_xproj (B, GEMM2)
__device__ uint32_t g_yf[NROWS * (size_t)DINNER / 2];        // y       (A, GEMM3)
__device__ uint32_t g_woutf[DMODEL * (size_t)DINNER / 2];    // W_out   (B, GEMM3)

// ---------------------------------------------------------------------------
// fp16 fragment layout, per 128(row) x 32(k) tile = 2048 u32 (8 KB).
//   A (m16n8k16): per 16x16 slab, 4 regs/lane:
//     reg0=(g,2t|2t+1) reg1=(g+8,..) reg2=(g,2t+8|2t+9) reg3=(g+8,..)
//   B (m16n8k16): per 8n x 16k slab, 2 regs/lane:
//     reg0=(2t|2t+1, g) reg1=(2t+8|2t+9, g)
// Index functions take EVEN k and return the u32 slot holding (k, k+1):
// low half = k (even), high half = k+1.
// ---------------------------------------------------------------------------
__device__ __forceinline__ int aidx16(int row, int k /*even*/) {
    int kstep = k >> 4, kin = k & 15;
    int mtile = row >> 4, r = row & 15;
    int lane = ((r & 7) << 2) | ((kin & 7) >> 1);
    int reg  = ((kin >> 3) << 1) | (r >> 3);
    return ((((kstep << 3) + mtile) << 5) + lane) * 4 + reg;
}
__device__ __forceinline__ int bidx16(int row, int k /*even*/) {
    int kstep = k >> 4, kin = k & 15;
    int ntile = row >> 3, nin = row & 7;
    int lane = (nin << 2) | ((kin & 7) >> 1);
    int reg  = kin >> 3;
    return ((((kstep << 4) + ntile) << 5) + lane) * 2 + reg;
}

__device__ __forceinline__ uint32_t pack_h2(float lo, float hi) {
    __half2 h = __floats2half2_rn(lo, hi);   // low 16 bits = first arg
    return *reinterpret_cast<uint32_t*>(&h);
}

__device__ __forceinline__ void mma16(float acc[4], const uint32_t a[4], const uint32_t b[2]) {
    asm volatile(
        "mma.sync.aligned.m16n8k16.row.col.f32.f16.f16.f32 "
        "{%0,%1,%2,%3}, {%4,%5,%6,%7}, {%8,%9}, {%0,%1,%2,%3};"
        : "+f"(acc[0]), "+f"(acc[1]), "+f"(acc[2]), "+f"(acc[3])
        : "r"(a[0]), "r"(a[1]), "r"(a[2]), "r"(a[3]), "r"(b[0]), "r"(b[1]));
}

#define CP_ASYNC16(dst_u32, src_ptr) \
    asm volatile("cp.async.cg.shared.global [%0], [%1], 16;" \
                 :: "r"(dst_u32), "l"(src_ptr) : "memory")
#define CP_COMMIT() asm volatile("cp.async.commit_group;" ::: "memory")
#define CP_WAIT0()  asm volatile("cp.async.wait_group 0;" ::: "memory")

__device__ __forceinline__ uint32_t smem_u32a(const void* p) {
    uint32_t a;
    asm("{ .reg .u64 t; cvta.to.shared.u64 t, %1; cvt.u32.u64 %0, t; }"
        : "=r"(a) : "l"(p));
    return a;
}

// ---------------------------------------------------------------------------
// fp16 GEMM: C[M,N] = A[M,K] * B[N,K]^T, fragment-major fp16 operands.
// CTA 128x128, BK=32, 256 threads, warp grid 2(m) x 4(n), warp 64x32.
// smem: 2 buffers x (A 2048 + B 2048 u32) = 32 KB static.
// ---------------------------------------------------------------------------
__global__ void __launch_bounds__(256, 2)
gemm_f16(const uint32_t* __restrict__ Af, const uint32_t* __restrict__ Bf,
         float* __restrict__ C, int M, int N, int KT /* = K/32 */)
{
    __shared__ uint32_t smem[8192];
    const int tid  = threadIdx.x;
    const int lane = tid & 31;
    const int warp = tid >> 5;
    const int wm   = warp >> 2;       // 0..1
    const int wn   = warp & 3;        // 0..3
    const int m0   = blockIdx.y * 128;
    const int n0   = blockIdx.x * 128;

    const uint32_t sb = smem_u32a(smem);
    const uint32_t* At = Af + (size_t)blockIdx.y * KT * 2048;
    const uint32_t* Bt = Bf + (size_t)blockIdx.x * KT * 2048;

    float acc[4][4][4];
#pragma unroll
    for (int i = 0; i < 4; i++)
#pragma unroll
        for (int j = 0; j < 4; j++)
#pragma unroll
            for (int q = 0; q < 4; q++) acc[i][j][q] = 0.f;

    // ---- prologue: stage tile 0 into buffer 0 (A 8KB + B 8KB)
#pragma unroll
    for (int i = 0; i < 2; i++) {
        const int slot = tid + 256 * i;                // float4 slot (0..511)
        CP_ASYNC16(sb + (uint32_t)slot * 16,          At + (size_t)slot * 4);
        CP_ASYNC16(sb + 8192u + (uint32_t)slot * 16,  Bt + (size_t)slot * 4);
    }
    CP_COMMIT();

    for (int kt = 0; kt < KT; ++kt) {
        CP_WAIT0();
        __syncthreads();

        // stage next tile into the other buffer (overlaps compute below)
        if (kt + 1 < KT) {
            const uint32_t boff = ((kt + 1) & 1) ? 16384u : 0u;   // bytes
            const uint32_t* An = At + (size_t)(kt + 1) * 2048;
            const uint32_t* Bn = Bt + (size_t)(kt + 1) * 2048;
#pragma unroll
            for (int i = 0; i < 2; i++) {
                const int slot = tid + 256 * i;
                CP_ASYNC16(sb + boff + (uint32_t)slot * 16,         An + (size_t)slot * 4);
                CP_ASYNC16(sb + boff + 8192u + (uint32_t)slot * 16, Bn + (size_t)slot * 4);
            }
            CP_COMMIT();
        }

        // ---- compute from buffer kt&1 (2 k-steps of 16)
        const uint32_t* Asb = smem + (kt & 1) * 4096;
        const uint32_t* Bsb = Asb + 2048;
#pragma unroll
        for (int ks = 0; ks < 2; ++ks) {
            uint32_t af[4][4];
            uint32_t bf[4][2];
#pragma unroll
            for (int im = 0; im < 4; ++im) {
                const int mt = wm * 4 + im;
                const uint4 t = *reinterpret_cast<const uint4*>(
                    &Asb[((((ks << 3) + mt) << 5) + lane) * 4]);
                af[im][0] = t.x; af[im][1] = t.y; af[im][2] = t.z; af[im][3] = t.w;
            }
#pragma unroll
            for (int jn = 0; jn < 4; ++jn) {
                const int nt = wn * 4 + jn;
                const uint2 t = *reinterpret_cast<const uint2*>(
                    &Bsb[((((ks << 4) + nt) << 5) + lane) * 2]);
                bf[jn][0] = t.x; bf[jn][1] = t.y;
            }
#pragma unroll
            for (int im = 0; im < 4; ++im)
#pragma unroll
                for (int jn = 0; jn < 4; ++jn)
                    mma16(acc[im][jn], af[im], bf[jn]);
        }
    }

    // ---- epilogue (C fragment layout identical to tf32 path)
    const int g = lane >> 2, t = lane & 3;
#pragma unroll
    for (int im = 0; im < 4; ++im) {
        const int mrow = m0 + wm * 64 + im * 16 + g;
#pragma unroll
        for (int jn = 0; jn < 4; ++jn) {
            const int nb = n0 + wn * 32 + jn * 8;
            if (nb < N) {   // N % 8 == 0 always
                float2 v0 = make_float2(acc[im][jn][0], acc[im][jn][1]);
                float2 v1 = make_float2(acc[im][jn][2], acc[im][jn][3]);
                *reinterpret_cast<float2*>(&C[(size_t)mrow * N + nb + 2 * t])       = v0;
                *reinterpret_cast<float2*>(&C[(size_t)(mrow + 8) * N + nb + 2 * t]) = v1;
            }
        }
    }
}

// ---------------------------------------------------------------------------
// Prep: fp16-round + permute into fragment-major layout
// ---------------------------------------------------------------------------
__global__ void __launch_bounds__(256)
prep_frag_a(const float* __restrict__ src, uint32_t* __restrict__ dst, int M, int K)
{
    const int idx = blockIdx.x * blockDim.x + threadIdx.x;  // M*K/4 threads
    const int kp = K >> 2;
    const int r  = idx / kp;
    const int kq = (idx - r * kp) << 2;
    if (r >= M) return;
    const float4 v = *reinterpret_cast<const float4*>(&src[(size_t)r * K + kq]);
    uint32_t* d = dst + ((size_t)((r >> 7) * (K >> 5) + (kq >> 5))) * 2048;
    const int rr = r & 127, kk = kq & 31;
    d[aidx16(rr, kk + 0)] = pack_h2(v.x, v.y);
    d[aidx16(rr, kk + 2)] = pack_h2(v.z, v.w);
}

__global__ void __launch_bounds__(256)
prep_frag_b(const float* __restrict__ src, uint32_t* __restrict__ dst,
            int Nr, int K, int Npad)
{
    const int idx = blockIdx.x * blockDim.x + threadIdx.x;  // Npad*K/4 threads
    const int kp = K >> 2;
    const int r  = idx / kp;
    const int kq = (idx - r * kp) << 2;
    if (r >= Npad) return;
    float4 v = make_float4(0.f, 0.f, 0.f, 0.f);
    if (r < Nr) v = *reinterpret_cast<const float4*>(&src[(size_t)r * K + kq]);
    uint32_t* d = dst + ((size_t)((r >> 7) * (K >> 5) + (kq >> 5))) * 2048;
    const int rr = r & 127, kk = kq & 31;
    d[bidx16(rr, kk + 0)] = pack_h2(v.x, v.y);
    d[bidx16(rr, kk + 2)] = pack_h2(v.z, v.w);
}

// ---------------------------------------------------------------------------
// Elementwise
// ---------------------------------------------------------------------------
__device__ __forceinline__ float siluf(float v)     { return v / (1.f + expf(-v)); }
__device__ __forceinline__ float softplusf(float v) { return fmaxf(v, 0.f) + log1pf(expf(-fabsf(v))); }

// xc = fp16(silu(conv(xb))), fragment-A layout (feeds GEMM2)
__global__ void __launch_bounds__(256)
conv_silu_kernel(const float* __restrict__ xz, const float* __restrict__ cw,
                 const float* __restrict__ cb, uint32_t* __restrict__ xcf)
{
    const int idx = blockIdx.x * blockDim.x + threadIdx.x;
    const int c4 = (idx & 511) << 2;
    const int r  = idx >> 9;
    if (r >= NROWS) return;
    const int l = r & (LSEQ - 1);

    const float4 bias = *reinterpret_cast<const float4*>(&cb[c4]);
    float a0 = bias.x, a1 = bias.y, a2 = bias.z, a3 = bias.w;

#pragma unroll
    for (int k = 0; k < 4; k++) {
        const int ls = l + k - 3;
        if (ls >= 0) {
            const float4 v = *reinterpret_cast<const float4*>(
                &xz[(size_t)(r + k - 3) * NXZ + c4]);
            a0 = fmaf(__ldg(&cw[(c4 + 0) * 4 + k]), v.x, a0);
            a1 = fmaf(__ldg(&cw[(c4 + 1) * 4 + k]), v.y, a1);
            a2 = fmaf(__ldg(&cw[(c4 + 2) * 4 + k]), v.z, a2);
            a3 = fmaf(__ldg(&cw[(c4 + 3) * 4 + k]), v.w, a3);
        }
    }
    uint32_t* d = xcf + ((size_t)((r >> 7) * (DINNER >> 5) + (c4 >> 5))) * 2048;
    const int rr = r & 127, kk = c4 & 31;
    d[aidx16(rr, kk + 0)] = pack_h2(siluf(a0), siluf(a1));
    d[aidx16(rr, kk + 2)] = pack_h2(siluf(a2), siluf(a3));
}

// y = fp16((softplus(dproj)*bc + D) * xc * silu(z)), fragment-A layout
__global__ void __launch_bounds__(128)
combine_kernel(const float* __restrict__ xz, const uint32_t* __restrict__ xcf,
               const float* __restrict__ proj, const float* __restrict__ D,
               uint32_t* __restrict__ yf)
{
    const int r   = blockIdx.x;
    const int tid = threadIdx.x;
    __shared__ float sbc;

    const float* prow = proj + (size_t)r * NPROJ;
    if (tid < 32) {
        float v = 0.f;
        if (tid < D_STATE) v = prow[tid] * prow[D_STATE + tid];
#pragma unroll
        for (int o = 8; o > 0; o >>= 1) v += __shfl_xor_sync(0xffffffffu, v, o);
        if (tid == 0) sbc = v;
    }
    __syncthreads();
    const float bc = sbc;

    const float* zrow = xz + (size_t)r * NXZ + DINNER;
    const int rr = r & 127;
    const size_t rowbase = ((size_t)(r >> 7) * (DINNER >> 5)) * 2048;

#pragma unroll
    for (int i = 0; i < 4; i++) {
        const int c = (i * 128 + tid) * 4;
        const float4 dp = *reinterpret_cast<const float4*>(&prow[2 * D_STATE + c]);
        const float4 zv = *reinterpret_cast<const float4*>(&zrow[c]);
        const float4 Dv = *reinterpret_cast<const float4*>(&D[c]);
        const size_t base = rowbase + (size_t)(c >> 5) * 2048;
        const int kk = c & 31;
        const int i0 = aidx16(rr, kk + 0);
        const int i1 = aidx16(rr, kk + 2);
        const __half2 h0 = *reinterpret_cast<const __half2*>(&xcf[base + i0]);
        const __half2 h1 = *reinterpret_cast<const __half2*>(&xcf[base + i1]);
        const float x0 = __low2float(h0),  x1 = __high2float(h0);
        const float x2 = __low2float(h1),  x3 = __high2float(h1);
        const float y0 = (softplusf(dp.x) * bc + Dv.x) * x0 * siluf(zv.x);
        const float y1 = (softplusf(dp.y) * bc + Dv.y) * x1 * siluf(zv.y);
        const float y2 = (softplusf(dp.z) * bc + Dv.z) * x2 * siluf(zv.z);
        const float y3 = (softplusf(dp.w) * bc + Dv.w) * x3 * siluf(zv.w);
        yf[base + i0] = pack_h2(y0, y1);
        yf[base + i1] = pack_h2(y2, y3);
    }
}

// ---------------------------------------------------------------------------
// Launch
// ---------------------------------------------------------------------------
extern "C" void kernel_launch(void* const* d_in, const int* in_sizes, int n_in,
                              void* d_out, int out_size)
{
    const float* x      = (const float*)d_in[0];
    const float* W_in   = (const float*)d_in[1];
    const float* conv_w = (const float*)d_in[2];
    const float* conv_b = (const float*)d_in[3];
    const float* W_xp   = (const float*)d_in[4];
    const float* D      = (const float*)d_in[5];
    const float* W_out  = (const float*)d_in[6];
    float* out = (float*)d_out;

    void *p_xz, *p_proj, *p_xf, *p_winf, *p_xcf, *p_wxpf, *p_yf, *p_woutf;
    cudaGetSymbolAddress(&p_xz,    g_xz);
    cudaGetSymbolAddress(&p_proj,  g_proj);
    cudaGetSymbolAddress(&p_xf,    g_xf);
    cudaGetSymbolAddress(&p_winf,  g_winf);
    cudaGetSymbolAddress(&p_xcf,   g_xcf);
    cudaGetSymbolAddress(&p_wxpf,  g_wxpf);
    cudaGetSymbolAddress(&p_yf,    g_yf);
    cudaGetSymbolAddress(&p_woutf, g_woutf);

    // Prep: fp16-round + fragment-permute the GEMM operands
    prep_frag_a<<<(NROWS * (DMODEL / 4)) / 256, 256>>>(x, (uint32_t*)p_xf, NROWS, DMODEL);
    prep_frag_b<<<(NXZ * (DMODEL / 4)) / 256, 256>>>(W_in, (uint32_t*)p_winf, NXZ, DMODEL, NXZ);
    prep_frag_b<<<(NPROJ_PAD * (DINNER / 4)) / 256, 256>>>(W_xp, (uint32_t*)p_wxpf, NPROJ, DINNER, NPROJ_PAD);
    prep_frag_b<<<(DMODEL * (DINNER / 4)) / 256, 256>>>(W_out, (uint32_t*)p_woutf, DMODEL, DINNER, DMODEL);

    // GEMM1: xz = x @ W_in^T   (8192 x 4096 x 1024)
    gemm_f16<<<dim3(NXZ / 128, NROWS / 128), 256>>>(
        (const uint32_t*)p_xf, (const uint32_t*)p_winf, (float*)p_xz,
        NROWS, NXZ, DMODEL / 32);

    // conv + SiLU -> xc (fp16 fragment layout)
    conv_silu_kernel<<<(NROWS * 512) / 256, 256>>>(
        (const float*)p_xz, conv_w, conv_b, (uint32_t*)p_xcf);

    // GEMM2: proj = xc @ W_xproj^T  (8192 x 2080 x 2048), frag N padded to 2176
    gemm_f16<<<dim3(NPROJ_PAD / 128, NROWS / 128), 256>>>(
        (const uint32_t*)p_xcf, (const uint32_t*)p_wxpf, (float*)p_proj,
        NROWS, NPROJ, DINNER / 32);

    // combine -> y (fp16 fragment layout)
    combine_kernel<<<NROWS, 128>>>(
        (const float*)p_xz, (const uint32_t*)p_xcf, (const float*)p_proj, D, (uint32_t*)p_yf);

    // GEMM3: out = y @ W_out^T   (8192 x 1024 x 2048)
    gemm_f16<<<dim3(DMODEL / 128, NROWS / 128), 256>>>(
        (const uint32_t*)p_yf, (const uint32_t*)p_woutf, out,
        NROWS, DMODEL, DINNER / 32);
}

// round 10
// speedup vs baseline: 1.7952x; 1.0263x over previous
#include <cuda_runtime.h>
#include <cuda_fp16.h>
#include <cstdint>

// ---------------------------------------------------------------------------
// SelectiveSSM on GB300 (base sm_103 target => mma.sync path).
// R10: 3-stage cp.async pipeline in the fp16 GEMM (wait_group 1) to hide
// copy latency. All other kernels byte-identical to passing R9 (672.7 us).
// ---------------------------------------------------------------------------

#define D_STATE 16
#define BSZ     2
#define LSEQ    4096
#define DMODEL  1024
#define DINNER  2048
#define NROWS   (BSZ * LSEQ)            // 8192
#define NXZ     (2 * DINNER)            // 4096
#define NPROJ   (2 * D_STATE + DINNER)  // 2080
#define NPROJ_PAD 2176                  // 17 * 128

// Scratch (device globals: allocation-free)
__device__ float g_xz[NROWS * (size_t)NXZ];        // GEMM1 out (normal layout)
__device__ float g_proj[NROWS * (size_t)NPROJ];    // GEMM2 out (normal layout)
// fragment-major fp16 operands (u32 = packed half2)
__device__ uint32_t g_xf[NROWS * (size_t)DMODEL / 2];        // x       (A, GEMM1)
__device__ uint32_t g_winf[NXZ * (size_t)DMODEL / 2];        // W_in    (B, GEMM1)
__device__ uint32_t g_xcf[NROWS * (size_t)DINNER / 2];       // xc      (A, GEMM2)
__device__ uint32_t g_wxpf[NPROJ_PAD * (size_t)DINNER / 2];  // W_xproj (B, GEMM2)
__device__ uint32_t g_yf[NROWS * (size_t)DINNER / 2];        // y       (A, GEMM3)
__device__ uint32_t g_woutf[DMODEL * (size_t)DINNER / 2];    // W_out   (B, GEMM3)

// ---------------------------------------------------------------------------
// fp16 fragment layout, per 128(row) x 32(k) tile = 2048 u32 (8 KB).
//   A (m16n8k16): per 16x16 slab, 4 regs/lane.
//   B (m16n8k16): per 8n x 16k slab, 2 regs/lane.
// Index functions take EVEN k and return the u32 slot holding (k, k+1).
// ---------------------------------------------------------------------------
__device__ __forceinline__ int aidx16(int row, int k /*even*/) {
    int kstep = k >> 4, kin = k & 15;
    int mtile = row >> 4, r = row & 15;
    int lane = ((r & 7) << 2) | ((kin & 7) >> 1);
    int reg  = ((kin >> 3) << 1) | (r >> 3);
    return ((((kstep << 3) + mtile) << 5) + lane) * 4 + reg;
}
__device__ __forceinline__ int bidx16(int row, int k /*even*/) {
    int kstep = k >> 4, kin = k & 15;
    int ntile = row >> 3, nin = row & 7;
    int lane = (nin << 2) | ((kin & 7) >> 1);
    int reg  = kin >> 3;
    return ((((kstep << 4) + ntile) << 5) + lane) * 2 + reg;
}

__device__ __forceinline__ uint32_t pack_h2(float lo, float hi) {
    __half2 h = __floats2half2_rn(lo, hi);   // low 16 bits = first arg
    return *reinterpret_cast<uint32_t*>(&h);
}

__device__ __forceinline__ void mma16(float acc[4], const uint32_t a[4], const uint32_t b[2]) {
    asm volatile(
        "mma.sync.aligned.m16n8k16.row.col.f32.f16.f16.f32 "
        "{%0,%1,%2,%3}, {%4,%5,%6,%7}, {%8,%9}, {%0,%1,%2,%3};"
        : "+f"(acc[0]), "+f"(acc[1]), "+f"(acc[2]), "+f"(acc[3])
        : "r"(a[0]), "r"(a[1]), "r"(a[2]), "r"(a[3]), "r"(b[0]), "r"(b[1]));
}

#define CP_ASYNC16(dst_u32, src_ptr) \
    asm volatile("cp.async.cg.shared.global [%0], [%1], 16;" \
                 :: "r"(dst_u32), "l"(src_ptr) : "memory")
#define CP_COMMIT() asm volatile("cp.async.commit_group;" ::: "memory")
#define CP_WAIT0()  asm volatile("cp.async.wait_group 0;" ::: "memory")
#define CP_WAIT1()  asm volatile("cp.async.wait_group 1;" ::: "memory")

__device__ __forceinline__ uint32_t smem_u32a(const void* p) {
    uint32_t a;
    asm("{ .reg .u64 t; cvta.to.shared.u64 t, %1; cvt.u32.u64 %0, t; }"
        : "=r"(a) : "l"(p));
    return a;
}

// ---------------------------------------------------------------------------
// fp16 GEMM: C[M,N] = A[M,K] * B[N,K]^T, fragment-major fp16 operands.
// CTA 128x128, BK=32, 256 threads, warp grid 2(m) x 4(n), warp 64x32.
// smem: 3 buffers x (A 2048 + B 2048 u32) = 48 KB static. 2 CTA/SM.
// 3-stage cp.async pipeline: one tile-copy always in flight during compute.
// ---------------------------------------------------------------------------
__global__ void __launch_bounds__(256, 2)
gemm_f16(const uint32_t* __restrict__ Af, const uint32_t* __restrict__ Bf,
         float* __restrict__ C, int M, int N, int KT /* = K/32 */)
{
    __shared__ uint32_t smem[12288];     // 3 x 4096 u32
    const int tid  = threadIdx.x;
    const int lane = tid & 31;
    const int warp = tid >> 5;
    const int wm   = warp >> 2;       // 0..1
    const int wn   = warp & 3;        // 0..3
    const int m0   = blockIdx.y * 128;
    const int n0   = blockIdx.x * 128;

    const uint32_t sb = smem_u32a(smem);
    const uint32_t* At = Af + (size_t)blockIdx.y * KT * 2048;
    const uint32_t* Bt = Bf + (size_t)blockIdx.x * KT * 2048;

    float acc[4][4][4];
#pragma unroll
    for (int i = 0; i < 4; i++)
#pragma unroll
        for (int j = 0; j < 4; j++)
#pragma unroll
            for (int q = 0; q < 4; q++) acc[i][j][q] = 0.f;

    // per-thread staging slots (2 x float4 per operand tile)
    const int s0 = tid, s1 = tid + 256;

    // ---- prologue: stage tiles 0 and 1 into buffers 0 and 1
    {
        CP_ASYNC16(sb + (uint32_t)s0 * 16,          At + (size_t)s0 * 4);
        CP_ASYNC16(sb + (uint32_t)s1 * 16,          At + (size_t)s1 * 4);
        CP_ASYNC16(sb + 8192u + (uint32_t)s0 * 16,  Bt + (size_t)s0 * 4);
        CP_ASYNC16(sb + 8192u + (uint32_t)s1 * 16,  Bt + (size_t)s1 * 4);
        CP_COMMIT();
        const uint32_t b1 = 16384u;
        const uint32_t* An = At + 2048;
        const uint32_t* Bn = Bt + 2048;
        CP_ASYNC16(sb + b1 + (uint32_t)s0 * 16,         An + (size_t)s0 * 4);
        CP_ASYNC16(sb + b1 + (uint32_t)s1 * 16,         An + (size_t)s1 * 4);
        CP_ASYNC16(sb + b1 + 8192u + (uint32_t)s0 * 16, Bn + (size_t)s0 * 4);
        CP_ASYNC16(sb + b1 + 8192u + (uint32_t)s1 * 16, Bn + (size_t)s1 * 4);
        CP_COMMIT();
    }

    int cur = 0, nxt = 2;                // buffer indices mod 3
    for (int kt = 0; kt < KT; ++kt) {
        if (kt + 1 < KT) CP_WAIT1(); else CP_WAIT0();
        __syncthreads();

        // stage tile kt+2 into buffer nxt (consumed 2 iters ago; sync above
        // guarantees all warps finished reading it)
        if (kt + 2 < KT) {
            const uint32_t boff = (uint32_t)nxt * 16384u;
            const uint32_t* An = At + (size_t)(kt + 2) * 2048;
            const uint32_t* Bn = Bt + (size_t)(kt + 2) * 2048;
            CP_ASYNC16(sb + boff + (uint32_t)s0 * 16,         An + (size_t)s0 * 4);
            CP_ASYNC16(sb + boff + (uint32_t)s1 * 16,         An + (size_t)s1 * 4);
            CP_ASYNC16(sb + boff + 8192u + (uint32_t)s0 * 16, Bn + (size_t)s0 * 4);
            CP_ASYNC16(sb + boff + 8192u + (uint32_t)s1 * 16, Bn + (size_t)s1 * 4);
            CP_COMMIT();
        }

        // ---- compute from buffer cur (2 k-steps of 16)
        const uint32_t* Asb = smem + cur * 4096;
        const uint32_t* Bsb = Asb + 2048;
#pragma unroll
        for (int ks = 0; ks < 2; ++ks) {
            uint32_t af[4][4];
            uint32_t bf[4][2];
#pragma unroll
            for (int im = 0; im < 4; ++im) {
                const int mt = wm * 4 + im;
                const uint4 t = *reinterpret_cast<const uint4*>(
                    &Asb[((((ks << 3) + mt) << 5) + lane) * 4]);
                af[im][0] = t.x; af[im][1] = t.y; af[im][2] = t.z; af[im][3] = t.w;
            }
#pragma unroll
            for (int jn = 0; jn < 4; ++jn) {
                const int nt = wn * 4 + jn;
                const uint2 t = *reinterpret_cast<const uint2*>(
                    &Bsb[((((ks << 4) + nt) << 5) + lane) * 2]);
                bf[jn][0] = t.x; bf[jn][1] = t.y;
            }
#pragma unroll
            for (int im = 0; im < 4; ++im)
#pragma unroll
                for (int jn = 0; jn < 4; ++jn)
                    mma16(acc[im][jn], af[im], bf[jn]);
        }

        cur = (cur == 2) ? 0 : cur + 1;
        nxt = (nxt == 2) ? 0 : nxt + 1;
    }

    // ---- epilogue (C fragment layout identical to R9)
    const int g = lane >> 2, t = lane & 3;
#pragma unroll
    for (int im = 0; im < 4; ++im) {
        const int mrow = m0 + wm * 64 + im * 16 + g;
#pragma unroll
        for (int jn = 0; jn < 4; ++jn) {
            const int nb = n0 + wn * 32 + jn * 8;
            if (nb < N) {   // N % 8 == 0 always
                float2 v0 = make_float2(acc[im][jn][0], acc[im][jn][1]);
                float2 v1 = make_float2(acc[im][jn][2], acc[im][jn][3]);
                *reinterpret_cast<float2*>(&C[(size_t)mrow * N + nb + 2 * t])       = v0;
                *reinterpret_cast<float2*>(&C[(size_t)(mrow + 8) * N + nb + 2 * t]) = v1;
            }
        }
    }
}

// ---------------------------------------------------------------------------
// Prep: fp16-round + permute into fragment-major layout (unchanged from R9)
// ---------------------------------------------------------------------------
__global__ void __launch_bounds__(256)
prep_frag_a(const float* __restrict__ src, uint32_t* __restrict__ dst, int M, int K)
{
    const int idx = blockIdx.x * blockDim.x + threadIdx.x;
    const int kp = K >> 2;
    const int r  = idx / kp;
    const int kq = (idx - r * kp) << 2;
    if (r >= M) return;
    const float4 v = *reinterpret_cast<const float4*>(&src[(size_t)r * K + kq]);
    uint32_t* d = dst + ((size_t)((r >> 7) * (K >> 5) + (kq >> 5))) * 2048;
    const int rr = r & 127, kk = kq & 31;
    d[aidx16(rr, kk + 0)] = pack_h2(v.x, v.y);
    d[aidx16(rr, kk + 2)] = pack_h2(v.z, v.w);
}

__global__ void __launch_bounds__(256)
prep_frag_b(const float* __restrict__ src, uint32_t* __restrict__ dst,
            int Nr, int K, int Npad)
{
    const int idx = blockIdx.x * blockDim.x + threadIdx.x;
    const int kp = K >> 2;
    const int r  = idx / kp;
    const int kq = (idx - r * kp) << 2;
    if (r >= Npad) return;
    float4 v = make_float4(0.f, 0.f, 0.f, 0.f);
    if (r < Nr) v = *reinterpret_cast<const float4*>(&src[(size_t)r * K + kq]);
    uint32_t* d = dst + ((size_t)((r >> 7) * (K >> 5) + (kq >> 5))) * 2048;
    const int rr = r & 127, kk = kq & 31;
    d[bidx16(rr, kk + 0)] = pack_h2(v.x, v.y);
    d[bidx16(rr, kk + 2)] = pack_h2(v.z, v.w);
}

// ---------------------------------------------------------------------------
// Elementwise (unchanged from R9)
// ---------------------------------------------------------------------------
__device__ __forceinline__ float siluf(float v)     { return v / (1.f + expf(-v)); }
__device__ __forceinline__ float softplusf(float v) { return fmaxf(v, 0.f) + log1pf(expf(-fabsf(v))); }

// xc = fp16(silu(conv(xb))), fragment-A layout (feeds GEMM2)
__global__ void __launch_bounds__(256)
conv_silu_kernel(const float* __restrict__ xz, const float* __restrict__ cw,
                 const float* __restrict__ cb, uint32_t* __restrict__ xcf)
{
    const int idx = blockIdx.x * blockDim.x + threadIdx.x;
    const int c4 = (idx & 511) << 2;
    const int r  = idx >> 9;
    if (r >= NROWS) return;
    const int l = r & (LSEQ - 1);

    const float4 bias = *reinterpret_cast<const float4*>(&cb[c4]);
    float a0 = bias.x, a1 = bias.y, a2 = bias.z, a3 = bias.w;

#pragma unroll
    for (int k = 0; k < 4; k++) {
        const int ls = l + k - 3;
        if (ls >= 0) {
            const float4 v = *reinterpret_cast<const float4*>(
                &xz[(size_t)(r + k - 3) * NXZ + c4]);
            a0 = fmaf(__ldg(&cw[(c4 + 0) * 4 + k]), v.x, a0);
            a1 = fmaf(__ldg(&cw[(c4 + 1) * 4 + k]), v.y, a1);
            a2 = fmaf(__ldg(&cw[(c4 + 2) * 4 + k]), v.z, a2);
            a3 = fmaf(__ldg(&cw[(c4 + 3) * 4 + k]), v.w, a3);
        }
    }
    uint32_t* d = xcf + ((size_t)((r >> 7) * (DINNER >> 5) + (c4 >> 5))) * 2048;
    const int rr = r & 127, kk = c4 & 31;
    d[aidx16(rr, kk + 0)] = pack_h2(siluf(a0), siluf(a1));
    d[aidx16(rr, kk + 2)] = pack_h2(siluf(a2), siluf(a3));
}

// y = fp16((softplus(dproj)*bc + D) * xc * silu(z)), fragment-A layout
__global__ void __launch_bounds__(128)
combine_kernel(const float* __restrict__ xz, const uint32_t* __restrict__ xcf,
               const float* __restrict__ proj, const float* __restrict__ D,
               uint32_t* __restrict__ yf)
{
    const int r   = blockIdx.x;
    const int tid = threadIdx.x;
    __shared__ float sbc;

    const float* prow = proj + (size_t)r * NPROJ;
    if (tid < 32) {
        float v = 0.f;
        if (tid < D_STATE) v = prow[tid] * prow[D_STATE + tid];
#pragma unroll
        for (int o = 8; o > 0; o >>= 1) v += __shfl_xor_sync(0xffffffffu, v, o);
        if (tid == 0) sbc = v;
    }
    __syncthreads();
    const float bc = sbc;

    const float* zrow = xz + (size_t)r * NXZ + DINNER;
    const int rr = r & 127;
    const size_t rowbase = ((size_t)(r >> 7) * (DINNER >> 5)) * 2048;

#pragma unroll
    for (int i = 0; i < 4; i++) {
        const int c = (i * 128 + tid) * 4;
        const float4 dp = *reinterpret_cast<const float4*>(&prow[2 * D_STATE + c]);
        const float4 zv = *reinterpret_cast<const float4*>(&zrow[c]);
        const float4 Dv = *reinterpret_cast<const float4*>(&D[c]);
        const size_t base = rowbase + (size_t)(c >> 5) * 2048;
        const int kk = c & 31;
        const int i0 = aidx16(rr, kk + 0);
        const int i1 = aidx16(rr, kk + 2);
        const __half2 h0 = *reinterpret_cast<const __half2*>(&xcf[base + i0]);
        const __half2 h1 = *reinterpret_cast<const __half2*>(&xcf[base + i1]);
        const float x0 = __low2float(h0),  x1 = __high2float(h0);
        const float x2 = __low2float(h1),  x3 = __high2float(h1);
        const float y0 = (softplusf(dp.x) * bc + Dv.x) * x0 * siluf(zv.x);
        const float y1 = (softplusf(dp.y) * bc + Dv.y) * x1 * siluf(zv.y);
        const float y2 = (softplusf(dp.z) * bc + Dv.z) * x2 * siluf(zv.z);
        const float y3 = (softplusf(dp.w) * bc + Dv.w) * x3 * siluf(zv.w);
        yf[base + i0] = pack_h2(y0, y1);
        yf[base + i1] = pack_h2(y2, y3);
    }
}

// ---------------------------------------------------------------------------
// Launch
// ---------------------------------------------------------------------------
extern "C" void kernel_launch(void* const* d_in, const int* in_sizes, int n_in,
                              void* d_out, int out_size)
{
    const float* x      = (const float*)d_in[0];
    const float* W_in   = (const float*)d_in[1];
    const float* conv_w = (const float*)d_in[2];
    const float* conv_b = (const float*)d_in[3];
    const float* W_xp   = (const float*)d_in[4];
    const float* D      = (const float*)d_in[5];
    const float* W_out  = (const float*)d_in[6];
    float* out = (float*)d_out;

    void *p_xz, *p_proj, *p_xf, *p_winf, *p_xcf, *p_wxpf, *p_yf, *p_woutf;
    cudaGetSymbolAddress(&p_xz,    g_xz);
    cudaGetSymbolAddress(&p_proj,  g_proj);
    cudaGetSymbolAddress(&p_xf,    g_xf);
    cudaGetSymbolAddress(&p_winf,  g_winf);
    cudaGetSymbolAddress(&p_xcf,   g_xcf);
    cudaGetSymbolAddress(&p_wxpf,  g_wxpf);
    cudaGetSymbolAddress(&p_yf,    g_yf);
    cudaGetSymbolAddress(&p_woutf, g_woutf);

    // Prep: fp16-round + fragment-permute the GEMM operands
    prep_frag_a<<<(NROWS * (DMODEL / 4)) / 256, 256>>>(x, (uint32_t*)p_xf, NROWS, DMODEL);
    prep_frag_b<<<(NXZ * (DMODEL / 4)) / 256, 256>>>(W_in, (uint32_t*)p_winf, NXZ, DMODEL, NXZ);
    prep_frag_b<<<(NPROJ_PAD * (DINNER / 4)) / 256, 256>>>(W_xp, (uint32_t*)p_wxpf, NPROJ, DINNER, NPROJ_PAD);
    prep_frag_b<<<(DMODEL * (DINNER / 4)) / 256, 256>>>(W_out, (uint32_t*)p_woutf, DMODEL, DINNER, DMODEL);

    // GEMM1: xz = x @ W_in^T   (8192 x 4096 x 1024)
    gemm_f16<<<dim3(NXZ / 128, NROWS / 128), 256>>>(
        (const uint32_t*)p_xf, (const uint32_t*)p_winf, (float*)p_xz,
        NROWS, NXZ, DMODEL / 32);

    // conv + SiLU -> xc (fp16 fragment layout)
    conv_silu_kernel<<<(NROWS * 512) / 256, 256>>>(
        (const float*)p_xz, conv_w, conv_b, (uint32_t*)p_xcf);

    // GEMM2: proj = xc @ W_xproj^T  (8192 x 2080 x 2048), frag N padded to 2176
    gemm_f16<<<dim3(NPROJ_PAD / 128, NROWS / 128), 256>>>(
        (const uint32_t*)p_xcf, (const uint32_t*)p_wxpf, (float*)p_proj,
        NROWS, NPROJ, DINNER / 32);

    // combine -> y (fp16 fragment layout)
    combine_kernel<<<NROWS, 128>>>(
        (const float*)p_xz, (const uint32_t*)p_xcf, (const float*)p_proj, D, (uint32_t*)p_yf);

    // GEMM3: out = y @ W_out^T   (8192 x 1024 x 2048)
    gemm_f16<<<dim3(DMODEL / 128, NROWS / 128), 256>>>(
        (const uint32_t*)p_yf, (const uint32_t*)p_woutf, out,
        NROWS, DMODEL, DINNER / 32);
}

// round 11
// speedup vs baseline: 1.9307x; 1.0755x over previous
#include <cuda_runtime.h>
#include <cuda_fp16.h>
#include <cstdint>

// ---------------------------------------------------------------------------
// SelectiveSSM on GB300 (base sm_103 target => mma.sync path).
// R11: fp16 GEMM switched to 4 warps x (64x64 warp tile), 128 threads/CTA,
// 2 CTA/SM — cuts smem fragment-read bytes per ktile 48KB -> 32KB to
// de-contend the L1/shared datapath from the tensor pipe.
// Everything else byte-identical to passing R10 (655.5 us).
// ---------------------------------------------------------------------------

#define D_STATE 16
#define BSZ     2
#define LSEQ    4096
#define DMODEL  1024
#define DINNER  2048
#define NROWS   (BSZ * LSEQ)            // 8192
#define NXZ     (2 * DINNER)            // 4096
#define NPROJ   (2 * D_STATE + DINNER)  // 2080
#define NPROJ_PAD 2176                  // 17 * 128

// Scratch (device globals: allocation-free)
__device__ float g_xz[NROWS * (size_t)NXZ];        // GEMM1 out (normal layout)
__device__ float g_proj[NROWS * (size_t)NPROJ];    // GEMM2 out (normal layout)
// fragment-major fp16 operands (u32 = packed half2)
__device__ uint32_t g_xf[NROWS * (size_t)DMODEL / 2];        // x       (A, GEMM1)
__device__ uint32_t g_winf[NXZ * (size_t)DMODEL / 2];        // W_in    (B, GEMM1)
__device__ uint32_t g_xcf[NROWS * (size_t)DINNER / 2];       // xc      (A, GEMM2)
__device__ uint32_t g_wxpf[NPROJ_PAD * (size_t)DINNER / 2];  // W_xproj (B, GEMM2)
__device__ uint32_t g_yf[NROWS * (size_t)DINNER / 2];        // y       (A, GEMM3)
__device__ uint32_t g_woutf[DMODEL * (size_t)DINNER / 2];    // W_out   (B, GEMM3)

// ---------------------------------------------------------------------------
// fp16 fragment layout, per 128(row) x 32(k) tile = 2048 u32 (8 KB).
//   A (m16n8k16): per 16x16 slab, 4 regs/lane.
//   B (m16n8k16): per 8n x 16k slab, 2 regs/lane.
// Index functions take EVEN k and return the u32 slot holding (k, k+1).
// ---------------------------------------------------------------------------
__device__ __forceinline__ int aidx16(int row, int k /*even*/) {
    int kstep = k >> 4, kin = k & 15;
    int mtile = row >> 4, r = row & 15;
    int lane = ((r & 7) << 2) | ((kin & 7) >> 1);
    int reg  = ((kin >> 3) << 1) | (r >> 3);
    return ((((kstep << 3) + mtile) << 5) + lane) * 4 + reg;
}
__device__ __forceinline__ int bidx16(int row, int k /*even*/) {
    int kstep = k >> 4, kin = k & 15;
    int ntile = row >> 3, nin = row & 7;
    int lane = (nin << 2) | ((kin & 7) >> 1);
    int reg  = kin >> 3;
    return ((((kstep << 4) + ntile) << 5) + lane) * 2 + reg;
}

__device__ __forceinline__ uint32_t pack_h2(float lo, float hi) {
    __half2 h = __floats2half2_rn(lo, hi);   // low 16 bits = first arg
    return *reinterpret_cast<uint32_t*>(&h);
}

__device__ __forceinline__ void mma16(float acc[4], const uint32_t a[4], const uint32_t b[2]) {
    asm volatile(
        "mma.sync.aligned.m16n8k16.row.col.f32.f16.f16.f32 "
        "{%0,%1,%2,%3}, {%4,%5,%6,%7}, {%8,%9}, {%0,%1,%2,%3};"
        : "+f"(acc[0]), "+f"(acc[1]), "+f"(acc[2]), "+f"(acc[3])
        : "r"(a[0]), "r"(a[1]), "r"(a[2]), "r"(a[3]), "r"(b[0]), "r"(b[1]));
}

#define CP_ASYNC16(dst_u32, src_ptr) \
    asm volatile("cp.async.cg.shared.global [%0], [%1], 16;" \
                 :: "r"(dst_u32), "l"(src_ptr) : "memory")
#define CP_COMMIT() asm volatile("cp.async.commit_group;" ::: "memory")
#define CP_WAIT0()  asm volatile("cp.async.wait_group 0;" ::: "memory")
#define CP_WAIT1()  asm volatile("cp.async.wait_group 1;" ::: "memory")

__device__ __forceinline__ uint32_t smem_u32a(const void* p) {
    uint32_t a;
    asm("{ .reg .u64 t; cvta.to.shared.u64 t, %1; cvt.u32.u64 %0, t; }"
        : "=r"(a) : "l"(p));
    return a;
}

// ---------------------------------------------------------------------------
// fp16 GEMM: C[M,N] = A[M,K] * B[N,K]^T, fragment-major fp16 operands.
// CTA 128x128, BK=32, 128 threads, warp grid 2(m) x 2(n), warp 64x64.
// smem: 3 buffers x (A 2048 + B 2048 u32) = 48 KB static. 2 CTA/SM.
// 3-stage cp.async pipeline: one tile-copy always in flight during compute.
// ---------------------------------------------------------------------------
__global__ void __launch_bounds__(128, 2)
gemm_f16(const uint32_t* __restrict__ Af, const uint32_t* __restrict__ Bf,
         float* __restrict__ C, int M, int N, int KT /* = K/32 */)
{
    __shared__ uint32_t smem[12288];     // 3 x 4096 u32
    const int tid  = threadIdx.x;
    const int lane = tid & 31;
    const int warp = tid >> 5;
    const int wm   = warp >> 1;       // 0..1
    const int wn   = warp & 1;        // 0..1
    const int m0   = blockIdx.y * 128;
    const int n0   = blockIdx.x * 128;

    const uint32_t sb = smem_u32a(smem);
    const uint32_t* At = Af + (size_t)blockIdx.y * KT * 2048;
    const uint32_t* Bt = Bf + (size_t)blockIdx.x * KT * 2048;

    float acc[4][8][4];
#pragma unroll
    for (int i = 0; i < 4; i++)
#pragma unroll
        for (int j = 0; j < 8; j++)
#pragma unroll
            for (int q = 0; q < 4; q++) acc[i][j][q] = 0.f;

    // per-thread staging slots: 4 x float4 per operand tile (128 threads)
    // A tile = 2048 u32 = 512 float4; B tile likewise.

    // ---- prologue: stage tiles 0 and 1 into buffers 0 and 1
#pragma unroll
    for (int i = 0; i < 4; i++) {
        const int s = tid + 128 * i;
        CP_ASYNC16(sb + (uint32_t)s * 16,          At + (size_t)s * 4);
        CP_ASYNC16(sb + 8192u + (uint32_t)s * 16,  Bt + (size_t)s * 4);
    }
    CP_COMMIT();
    {
        const uint32_t b1 = 16384u;
        const uint32_t* An = At + 2048;
        const uint32_t* Bn = Bt + 2048;
#pragma unroll
        for (int i = 0; i < 4; i++) {
            const int s = tid + 128 * i;
            CP_ASYNC16(sb + b1 + (uint32_t)s * 16,         An + (size_t)s * 4);
            CP_ASYNC16(sb + b1 + 8192u + (uint32_t)s * 16, Bn + (size_t)s * 4);
        }
        CP_COMMIT();
    }

    int cur = 0, nxt = 2;                // buffer indices mod 3
    for (int kt = 0; kt < KT; ++kt) {
        if (kt + 1 < KT) CP_WAIT1(); else CP_WAIT0();
        __syncthreads();

        // stage tile kt+2 into buffer nxt (consumed 2 iters ago)
        if (kt + 2 < KT) {
            const uint32_t boff = (uint32_t)nxt * 16384u;
            const uint32_t* An = At + (size_t)(kt + 2) * 2048;
            const uint32_t* Bn = Bt + (size_t)(kt + 2) * 2048;
#pragma unroll
            for (int i = 0; i < 4; i++) {
                const int s = tid + 128 * i;
                CP_ASYNC16(sb + boff + (uint32_t)s * 16,         An + (size_t)s * 4);
                CP_ASYNC16(sb + boff + 8192u + (uint32_t)s * 16, Bn + (size_t)s * 4);
            }
            CP_COMMIT();
        }

        // ---- compute from buffer cur (2 k-steps of 16), warp tile 64x64
        const uint32_t* Asb = smem + cur * 4096;
        const uint32_t* Bsb = Asb + 2048;
#pragma unroll
        for (int ks = 0; ks < 2; ++ks) {
            uint32_t af[4][4];
            uint32_t bf[8][2];
#pragma unroll
            for (int im = 0; im < 4; ++im) {
                const int mt = wm * 4 + im;
                const uint4 t = *reinterpret_cast<const uint4*>(
                    &Asb[((((ks << 3) + mt) << 5) + lane) * 4]);
                af[im][0] = t.x; af[im][1] = t.y; af[im][2] = t.z; af[im][3] = t.w;
            }
#pragma unroll
            for (int jn = 0; jn < 8; ++jn) {
                const int nt = wn * 8 + jn;
                const uint2 t = *reinterpret_cast<const uint2*>(
                    &Bsb[((((ks << 4) + nt) << 5) + lane) * 2]);
                bf[jn][0] = t.x; bf[jn][1] = t.y;
            }
#pragma unroll
            for (int im = 0; im < 4; ++im)
#pragma unroll
                for (int jn = 0; jn < 8; ++jn)
                    mma16(acc[im][jn], af[im], bf[jn]);
        }

        cur = (cur == 2) ? 0 : cur + 1;
        nxt = (nxt == 2) ? 0 : nxt + 1;
    }

    // ---- epilogue (same C fragment layout; warp covers 64 rows x 64 cols)
    const int g = lane >> 2, t = lane & 3;
#pragma unroll
    for (int im = 0; im < 4; ++im) {
        const int mrow = m0 + wm * 64 + im * 16 + g;
#pragma unroll
        for (int jn = 0; jn < 8; ++jn) {
            const int nb = n0 + wn * 64 + jn * 8;
            if (nb < N) {   // N % 8 == 0 always
                float2 v0 = make_float2(acc[im][jn][0], acc[im][jn][1]);
                float2 v1 = make_float2(acc[im][jn][2], acc[im][jn][3]);
                *reinterpret_cast<float2*>(&C[(size_t)mrow * N + nb + 2 * t])       = v0;
                *reinterpret_cast<float2*>(&C[(size_t)(mrow + 8) * N + nb + 2 * t]) = v1;
            }
        }
    }
}

// ---------------------------------------------------------------------------
// Prep: fp16-round + permute into fragment-major layout (unchanged)
// ---------------------------------------------------------------------------
__global__ void __launch_bounds__(256)
prep_frag_a(const float* __restrict__ src, uint32_t* __restrict__ dst, int M, int K)
{
    const int idx = blockIdx.x * blockDim.x + threadIdx.x;
    const int kp = K >> 2;
    const int r  = idx / kp;
    const int kq = (idx - r * kp) << 2;
    if (r >= M) return;
    const float4 v = *reinterpret_cast<const float4*>(&src[(size_t)r * K + kq]);
    uint32_t* d = dst + ((size_t)((r >> 7) * (K >> 5) + (kq >> 5))) * 2048;
    const int rr = r & 127, kk = kq & 31;
    d[aidx16(rr, kk + 0)] = pack_h2(v.x, v.y);
    d[aidx16(rr, kk + 2)] = pack_h2(v.z, v.w);
}

__global__ void __launch_bounds__(256)
prep_frag_b(const float* __restrict__ src, uint32_t* __restrict__ dst,
            int Nr, int K, int Npad)
{
    const int idx = blockIdx.x * blockDim.x + threadIdx.x;
    const int kp = K >> 2;
    const int r  = idx / kp;
    const int kq = (idx - r * kp) << 2;
    if (r >= Npad) return;
    float4 v = make_float4(0.f, 0.f, 0.f, 0.f);
    if (r < Nr) v = *reinterpret_cast<const float4*>(&src[(size_t)r * K + kq]);
    uint32_t* d = dst + ((size_t)((r >> 7) * (K >> 5) + (kq >> 5))) * 2048;
    const int rr = r & 127, kk = kq & 31;
    d[bidx16(rr, kk + 0)] = pack_h2(v.x, v.y);
    d[bidx16(rr, kk + 2)] = pack_h2(v.z, v.w);
}

// ---------------------------------------------------------------------------
// Elementwise (unchanged)
// ---------------------------------------------------------------------------
__device__ __forceinline__ float siluf(float v)     { return v / (1.f + expf(-v)); }
__device__ __forceinline__ float softplusf(float v) { return fmaxf(v, 0.f) + log1pf(expf(-fabsf(v))); }

// xc = fp16(silu(conv(xb))), fragment-A layout (feeds GEMM2)
__global__ void __launch_bounds__(256)
conv_silu_kernel(const float* __restrict__ xz, const float* __restrict__ cw,
                 const float* __restrict__ cb, uint32_t* __restrict__ xcf)
{
    const int idx = blockIdx.x * blockDim.x + threadIdx.x;
    const int c4 = (idx & 511) << 2;
    const int r  = idx >> 9;
    if (r >= NROWS) return;
    const int l = r & (LSEQ - 1);

    const float4 bias = *reinterpret_cast<const float4*>(&cb[c4]);
    float a0 = bias.x, a1 = bias.y, a2 = bias.z, a3 = bias.w;

#pragma unroll
    for (int k = 0; k < 4; k++) {
        const int ls = l + k - 3;
        if (ls >= 0) {
            const float4 v = *reinterpret_cast<const float4*>(
                &xz[(size_t)(r + k - 3) * NXZ + c4]);
            a0 = fmaf(__ldg(&cw[(c4 + 0) * 4 + k]), v.x, a0);
            a1 = fmaf(__ldg(&cw[(c4 + 1) * 4 + k]), v.y, a1);
            a2 = fmaf(__ldg(&cw[(c4 + 2) * 4 + k]), v.z, a2);
            a3 = fmaf(__ldg(&cw[(c4 + 3) * 4 + k]), v.w, a3);
        }
    }
    uint32_t* d = xcf + ((size_t)((r >> 7) * (DINNER >> 5) + (c4 >> 5))) * 2048;
    const int rr = r & 127, kk = c4 & 31;
    d[aidx16(rr, kk + 0)] = pack_h2(siluf(a0), siluf(a1));
    d[aidx16(rr, kk + 2)] = pack_h2(siluf(a2), siluf(a3));
}

// y = fp16((softplus(dproj)*bc + D) * xc * silu(z)), fragment-A layout
__global__ void __launch_bounds__(128)
combine_kernel(const float* __restrict__ xz, const uint32_t* __restrict__ xcf,
               const float* __restrict__ proj, const float* __restrict__ D,
               uint32_t* __restrict__ yf)
{
    const int r   = blockIdx.x;
    const int tid = threadIdx.x;
    __shared__ float sbc;

    const float* prow = proj + (size_t)r * NPROJ;
    if (tid < 32) {
        float v = 0.f;
        if (tid < D_STATE) v = prow[tid] * prow[D_STATE + tid];
#pragma unroll
        for (int o = 8; o > 0; o >>= 1) v += __shfl_xor_sync(0xffffffffu, v, o);
        if (tid == 0) sbc = v;
    }
    __syncthreads();
    const float bc = sbc;

    const float* zrow = xz + (size_t)r * NXZ + DINNER;
    const int rr = r & 127;
    const size_t rowbase = ((size_t)(r >> 7) * (DINNER >> 5)) * 2048;

#pragma unroll
    for (int i = 0; i < 4; i++) {
        const int c = (i * 128 + tid) * 4;
        const float4 dp = *reinterpret_cast<const float4*>(&prow[2 * D_STATE + c]);
        const float4 zv = *reinterpret_cast<const float4*>(&zrow[c]);
        const float4 Dv = *reinterpret_cast<const float4*>(&D[c]);
        const size_t base = rowbase + (size_t)(c >> 5) * 2048;
        const int kk = c & 31;
        const int i0 = aidx16(rr, kk + 0);
        const int i1 = aidx16(rr, kk + 2);
        const __half2 h0 = *reinterpret_cast<const __half2*>(&xcf[base + i0]);
        const __half2 h1 = *reinterpret_cast<const __half2*>(&xcf[base + i1]);
        const float x0 = __low2float(h0),  x1 = __high2float(h0);
        const float x2 = __low2float(h1),  x3 = __high2float(h1);
        const float y0 = (softplusf(dp.x) * bc + Dv.x) * x0 * siluf(zv.x);
        const float y1 = (softplusf(dp.y) * bc + Dv.y) * x1 * siluf(zv.y);
        const float y2 = (softplusf(dp.z) * bc + Dv.z) * x2 * siluf(zv.z);
        const float y3 = (softplusf(dp.w) * bc + Dv.w) * x3 * siluf(zv.w);
        yf[base + i0] = pack_h2(y0, y1);
        yf[base + i1] = pack_h2(y2, y3);
    }
}

// ---------------------------------------------------------------------------
// Launch
// ---------------------------------------------------------------------------
extern "C" void kernel_launch(void* const* d_in, const int* in_sizes, int n_in,
                              void* d_out, int out_size)
{
    const float* x      = (const float*)d_in[0];
    const float* W_in   = (const float*)d_in[1];
    const float* conv_w = (const float*)d_in[2];
    const float* conv_b = (const float*)d_in[3];
    const float* W_xp   = (const float*)d_in[4];
    const float* D      = (const float*)d_in[5];
    const float* W_out  = (const float*)d_in[6];
    float* out = (float*)d_out;

    void *p_xz, *p_proj, *p_xf, *p_winf, *p_xcf, *p_wxpf, *p_yf, *p_woutf;
    cudaGetSymbolAddress(&p_xz,    g_xz);
    cudaGetSymbolAddress(&p_proj,  g_proj);
    cudaGetSymbolAddress(&p_xf,    g_xf);
    cudaGetSymbolAddress(&p_winf,  g_winf);
    cudaGetSymbolAddress(&p_xcf,   g_xcf);
    cudaGetSymbolAddress(&p_wxpf,  g_wxpf);
    cudaGetSymbolAddress(&p_yf,    g_yf);
    cudaGetSymbolAddress(&p_woutf, g_woutf);

    // Prep: fp16-round + fragment-permute the GEMM operands
    prep_frag_a<<<(NROWS * (DMODEL / 4)) / 256, 256>>>(x, (uint32_t*)p_xf, NROWS, DMODEL);
    prep_frag_b<<<(NXZ * (DMODEL / 4)) / 256, 256>>>(W_in, (uint32_t*)p_winf, NXZ, DMODEL, NXZ);
    prep_frag_b<<<(NPROJ_PAD * (DINNER / 4)) / 256, 256>>>(W_xp, (uint32_t*)p_wxpf, NPROJ, DINNER, NPROJ_PAD);
    prep_frag_b<<<(DMODEL * (DINNER / 4)) / 256, 256>>>(W_out, (uint32_t*)p_woutf, DMODEL, DINNER, DMODEL);

    // GEMM1: xz = x @ W_in^T   (8192 x 4096 x 1024)
    gemm_f16<<<dim3(NXZ / 128, NROWS / 128), 128>>>(
        (const uint32_t*)p_xf, (const uint32_t*)p_winf, (float*)p_xz,
        NROWS, NXZ, DMODEL / 32);

    // conv + SiLU -> xc (fp16 fragment layout)
    conv_silu_kernel<<<(NROWS * 512) / 256, 256>>>(
        (const float*)p_xz, conv_w, conv_b, (uint32_t*)p_xcf);

    // GEMM2: proj = xc @ W_xproj^T  (8192 x 2080 x 2048), frag N padded to 2176
    gemm_f16<<<dim3(NPROJ_PAD / 128, NROWS / 128), 128>>>(
        (const uint32_t*)p_xcf, (const uint32_t*)p_wxpf, (float*)p_proj,
        NROWS, NPROJ, DINNER / 32);

    // combine -> y (fp16 fragment layout)
    combine_kernel<<<NROWS, 128>>>(
        (const float*)p_xz, (const uint32_t*)p_xcf, (const float*)p_proj, D, (uint32_t*)p_yf);

    // GEMM3: out = y @ W_out^T   (8192 x 1024 x 2048)
    gemm_f16<<<dim3(DMODEL / 128, NROWS / 128), 128>>>(
        (const uint32_t*)p_yf, (const uint32_t*)p_woutf, out,
        NROWS, DMODEL, DINNER / 32);
}

// round 12
// speedup vs baseline: 1.9377x; 1.0036x over previous
#include <cuda_runtime.h>
#include <cuda_fp16.h>
#include <cstdint>

// ---------------------------------------------------------------------------
// SelectiveSSM on GB300 (base sm_103 target => mma.sync path).
// R12 over passing R11 (609.4 us):
//   1. GEMM1 writes xz as fp16 (halves 200MB of DRAM traffic); conv/combine
//      read __half2. Template<HALF_OUT> epilogue.
//   2. 4-stage cp.async pipeline (stage-ahead 3, wait_group 2 steady state)
//      to keep two tile-copies in flight and absorb L2 jitter.
// GEMM compute loop / fragment layouts / preps unchanged.
// ---------------------------------------------------------------------------

#define D_STATE 16
#define BSZ     2
#define LSEQ    4096
#define DMODEL  1024
#define DINNER  2048
#define NROWS   (BSZ * LSEQ)            // 8192
#define NXZ     (2 * DINNER)            // 4096
#define NPROJ   (2 * D_STATE + DINNER)  // 2080
#define NPROJ_PAD 2176                  // 17 * 128

// Scratch (device globals: allocation-free)
__device__ __half g_xz[NROWS * (size_t)NXZ];       // GEMM1 out (fp16, normal layout)
__device__ float  g_proj[NROWS * (size_t)NPROJ];   // GEMM2 out (fp32, normal layout)
// fragment-major fp16 operands (u32 = packed half2)
__device__ uint32_t g_xf[NROWS * (size_t)DMODEL / 2];        // x       (A, GEMM1)
__device__ uint32_t g_winf[NXZ * (size_t)DMODEL / 2];        // W_in    (B, GEMM1)
__device__ uint32_t g_xcf[NROWS * (size_t)DINNER / 2];       // xc      (A, GEMM2)
__device__ uint32_t g_wxpf[NPROJ_PAD * (size_t)DINNER / 2];  // W_xproj (B, GEMM2)
__device__ uint32_t g_yf[NROWS * (size_t)DINNER / 2];        // y       (A, GEMM3)
__device__ uint32_t g_woutf[DMODEL * (size_t)DINNER / 2];    // W_out   (B, GEMM3)

// ---------------------------------------------------------------------------
// fp16 fragment layout, per 128(row) x 32(k) tile = 2048 u32 (8 KB).
// Index functions take EVEN k and return the u32 slot holding (k, k+1).
// ---------------------------------------------------------------------------
__device__ __forceinline__ int aidx16(int row, int k /*even*/) {
    int kstep = k >> 4, kin = k & 15;
    int mtile = row >> 4, r = row & 15;
    int lane = ((r & 7) << 2) | ((kin & 7) >> 1);
    int reg  = ((kin >> 3) << 1) | (r >> 3);
    return ((((kstep << 3) + mtile) << 5) + lane) * 4 + reg;
}
__device__ __forceinline__ int bidx16(int row, int k /*even*/) {
    int kstep = k >> 4, kin = k & 15;
    int ntile = row >> 3, nin = row & 7;
    int lane = (nin << 2) | ((kin & 7) >> 1);
    int reg  = kin >> 3;
    return ((((kstep << 4) + ntile) << 5) + lane) * 2 + reg;
}

__device__ __forceinline__ uint32_t pack_h2(float lo, float hi) {
    __half2 h = __floats2half2_rn(lo, hi);   // low 16 bits = first arg
    return *reinterpret_cast<uint32_t*>(&h);
}

__device__ __forceinline__ void mma16(float acc[4], const uint32_t a[4], const uint32_t b[2]) {
    asm volatile(
        "mma.sync.aligned.m16n8k16.row.col.f32.f16.f16.f32 "
        "{%0,%1,%2,%3}, {%4,%5,%6,%7}, {%8,%9}, {%0,%1,%2,%3};"
        : "+f"(acc[0]), "+f"(acc[1]), "+f"(acc[2]), "+f"(acc[3])
        : "r"(a[0]), "r"(a[1]), "r"(a[2]), "r"(a[3]), "r"(b[0]), "r"(b[1]));
}

#define CP_ASYNC16(dst_u32, src_ptr) \
    asm volatile("cp.async.cg.shared.global [%0], [%1], 16;" \
                 :: "r"(dst_u32), "l"(src_ptr) : "memory")
#define CP_COMMIT() asm volatile("cp.async.commit_group;" ::: "memory")
#define CP_WAIT0()  asm volatile("cp.async.wait_group 0;" ::: "memory")
#define CP_WAIT1()  asm volatile("cp.async.wait_group 1;" ::: "memory")
#define CP_WAIT2()  asm volatile("cp.async.wait_group 2;" ::: "memory")

__device__ __forceinline__ uint32_t smem_u32a(const void* p) {
    uint32_t a;
    asm("{ .reg .u64 t; cvta.to.shared.u64 t, %1; cvt.u32.u64 %0, t; }"
        : "=r"(a) : "l"(p));
    return a;
}

// ---------------------------------------------------------------------------
// fp16 GEMM: C[M,N] = A[M,K] * B[N,K]^T, fragment-major fp16 operands.
// CTA 128x128, BK=32, 128 threads, warp grid 2x2, warp tile 64x64.
// smem: 4 buffers x 16 KB = 64 KB dynamic. 2 CTA/SM.
// 4-stage pipeline: stage-ahead 3, wait_group 2 steady state.
// HALF_OUT: write C as fp16 (__half) instead of fp32.
// ---------------------------------------------------------------------------
template<bool HALF_OUT>
__global__ void __launch_bounds__(128, 2)
gemm_f16(const uint32_t* __restrict__ Af, const uint32_t* __restrict__ Bf,
         void* __restrict__ Cv, int M, int N, int KT /* = K/32 */)
{
    extern __shared__ uint32_t smem[];   // 4 x 4096 u32
    const int tid  = threadIdx.x;
    const int lane = tid & 31;
    const int warp = tid >> 5;
    const int wm   = warp >> 1;       // 0..1
    const int wn   = warp & 1;        // 0..1
    const int m0   = blockIdx.y * 128;
    const int n0   = blockIdx.x * 128;

    const uint32_t sb = smem_u32a(smem);
    const uint32_t* At = Af + (size_t)blockIdx.y * KT * 2048;
    const uint32_t* Bt = Bf + (size_t)blockIdx.x * KT * 2048;

    float acc[4][8][4];
#pragma unroll
    for (int i = 0; i < 4; i++)
#pragma unroll
        for (int j = 0; j < 8; j++)
#pragma unroll
            for (int q = 0; q < 4; q++) acc[i][j][q] = 0.f;

    // ---- prologue: stage tiles 0..2 into buffers 0..2 (stage-ahead 3)
#pragma unroll
    for (int p = 0; p < 3; p++) {
        if (p < KT) {
            const uint32_t boff = (uint32_t)p * 16384u;
            const uint32_t* An = At + (size_t)p * 2048;
            const uint32_t* Bn = Bt + (size_t)p * 2048;
#pragma unroll
            for (int i = 0; i < 4; i++) {
                const int s = tid + 128 * i;
                CP_ASYNC16(sb + boff + (uint32_t)s * 16,         An + (size_t)s * 4);
                CP_ASYNC16(sb + boff + 8192u + (uint32_t)s * 16, Bn + (size_t)s * 4);
            }
            CP_COMMIT();
        }
    }

    for (int kt = 0; kt < KT; ++kt) {
        // groups committed after tile kt: min(2, KT-1-kt) — clamp the wait
        const int remaining = KT - 1 - kt;
        if (remaining >= 2)      CP_WAIT2();
        else if (remaining == 1) CP_WAIT1();
        else                     CP_WAIT0();
        __syncthreads();

        // stage tile kt+3 into buffer (kt+3)&3 (consumed at iter kt-1;
        // the barrier above covers those reads)
        if (kt + 3 < KT) {
            const uint32_t boff = (uint32_t)((kt + 3) & 3) * 16384u;
            const uint32_t* An = At + (size_t)(kt + 3) * 2048;
            const uint32_t* Bn = Bt + (size_t)(kt + 3) * 2048;
#pragma unroll
            for (int i = 0; i < 4; i++) {
                const int s = tid + 128 * i;
                CP_ASYNC16(sb + boff + (uint32_t)s * 16,         An + (size_t)s * 4);
                CP_ASYNC16(sb + boff + 8192u + (uint32_t)s * 16, Bn + (size_t)s * 4);
            }
            CP_COMMIT();
        }

        // ---- compute from buffer kt&3 (2 k-steps of 16), warp tile 64x64
        const uint32_t* Asb = smem + (kt & 3) * 4096;
        const uint32_t* Bsb = Asb + 2048;
#pragma unroll
        for (int ks = 0; ks < 2; ++ks) {
            uint32_t af[4][4];
            uint32_t bf[8][2];
#pragma unroll
            for (int im = 0; im < 4; ++im) {
                const int mt = wm * 4 + im;
                const uint4 t = *reinterpret_cast<const uint4*>(
                    &Asb[((((ks << 3) + mt) << 5) + lane) * 4]);
                af[im][0] = t.x; af[im][1] = t.y; af[im][2] = t.z; af[im][3] = t.w;
            }
#pragma unroll
            for (int jn = 0; jn < 8; ++jn) {
                const int nt = wn * 8 + jn;
                const uint2 t = *reinterpret_cast<const uint2*>(
                    &Bsb[((((ks << 4) + nt) << 5) + lane) * 2]);
                bf[jn][0] = t.x; bf[jn][1] = t.y;
            }
#pragma unroll
            for (int im = 0; im < 4; ++im)
#pragma unroll
                for (int jn = 0; jn < 8; ++jn)
                    mma16(acc[im][jn], af[im], bf[jn]);
        }
    }

    // ---- epilogue (C fragment layout as before; fp16 or fp32 output)
    const int g = lane >> 2, t = lane & 3;
#pragma unroll
    for (int im = 0; im < 4; ++im) {
        const int mrow = m0 + wm * 64 + im * 16 + g;
#pragma unroll
        for (int jn = 0; jn < 8; ++jn) {
            const int nb = n0 + wn * 64 + jn * 8;
            if (nb < N) {   // N % 8 == 0 always
                if (HALF_OUT) {
                    __half* C = (__half*)Cv;
                    *reinterpret_cast<__half2*>(&C[(size_t)mrow * N + nb + 2 * t]) =
                        __floats2half2_rn(acc[im][jn][0], acc[im][jn][1]);
                    *reinterpret_cast<__half2*>(&C[(size_t)(mrow + 8) * N + nb + 2 * t]) =
                        __floats2half2_rn(acc[im][jn][2], acc[im][jn][3]);
                } else {
                    float* C = (float*)Cv;
                    float2 v0 = make_float2(acc[im][jn][0], acc[im][jn][1]);
                    float2 v1 = make_float2(acc[im][jn][2], acc[im][jn][3]);
                    *reinterpret_cast<float2*>(&C[(size_t)mrow * N + nb + 2 * t])       = v0;
                    *reinterpret_cast<float2*>(&C[(size_t)(mrow + 8) * N + nb + 2 * t]) = v1;
                }
            }
        }
    }
}

// ---------------------------------------------------------------------------
// Prep: fp16-round + permute into fragment-major layout (unchanged)
// ---------------------------------------------------------------------------
__global__ void __launch_bounds__(256)
prep_frag_a(const float* __restrict__ src, uint32_t* __restrict__ dst, int M, int K)
{
    const int idx = blockIdx.x * blockDim.x + threadIdx.x;
    const int kp = K >> 2;
    const int r  = idx / kp;
    const int kq = (idx - r * kp) << 2;
    if (r >= M) return;
    const float4 v = *reinterpret_cast<const float4*>(&src[(size_t)r * K + kq]);
    uint32_t* d = dst + ((size_t)((r >> 7) * (K >> 5) + (kq >> 5))) * 2048;
    const int rr = r & 127, kk = kq & 31;
    d[aidx16(rr, kk + 0)] = pack_h2(v.x, v.y);
    d[aidx16(rr, kk + 2)] = pack_h2(v.z, v.w);
}

__global__ void __launch_bounds__(256)
prep_frag_b(const float* __restrict__ src, uint32_t* __restrict__ dst,
            int Nr, int K, int Npad)
{
    const int idx = blockIdx.x * blockDim.x + threadIdx.x;
    const int kp = K >> 2;
    const int r  = idx / kp;
    const int kq = (idx - r * kp) << 2;
    if (r >= Npad) return;
    float4 v = make_float4(0.f, 0.f, 0.f, 0.f);
    if (r < Nr) v = *reinterpret_cast<const float4*>(&src[(size_t)r * K + kq]);
    uint32_t* d = dst + ((size_t)((r >> 7) * (K >> 5) + (kq >> 5))) * 2048;
    const int rr = r & 127, kk = kq & 31;
    d[bidx16(rr, kk + 0)] = pack_h2(v.x, v.y);
    d[bidx16(rr, kk + 2)] = pack_h2(v.z, v.w);
}

// ---------------------------------------------------------------------------
// Elementwise (xz now fp16)
// ---------------------------------------------------------------------------
__device__ __forceinline__ float siluf(float v)     { return v / (1.f + expf(-v)); }
__device__ __forceinline__ float softplusf(float v) { return fmaxf(v, 0.f) + log1pf(expf(-fabsf(v))); }

// xc = fp16(silu(conv(xb))), fragment-A layout (feeds GEMM2); xb read as fp16
__global__ void __launch_bounds__(256)
conv_silu_kernel(const __half* __restrict__ xz, const float* __restrict__ cw,
                 const float* __restrict__ cb, uint32_t* __restrict__ xcf)
{
    const int idx = blockIdx.x * blockDim.x + threadIdx.x;
    const int c4 = (idx & 511) << 2;
    const int r  = idx >> 9;
    if (r >= NROWS) return;
    const int l = r & (LSEQ - 1);

    const float4 bias = *reinterpret_cast<const float4*>(&cb[c4]);
    float a0 = bias.x, a1 = bias.y, a2 = bias.z, a3 = bias.w;

#pragma unroll
    for (int k = 0; k < 4; k++) {
        const int ls = l + k - 3;
        if (ls >= 0) {
            const __half2* p = reinterpret_cast<const __half2*>(
                &xz[(size_t)(r + k - 3) * NXZ + c4]);
            const float2 u0 = __half22float2(p[0]);
            const float2 u1 = __half22float2(p[1]);
            a0 = fmaf(__ldg(&cw[(c4 + 0) * 4 + k]), u0.x, a0);
            a1 = fmaf(__ldg(&cw[(c4 + 1) * 4 + k]), u0.y, a1);
            a2 = fmaf(__ldg(&cw[(c4 + 2) * 4 + k]), u1.x, a2);
            a3 = fmaf(__ldg(&cw[(c4 + 3) * 4 + k]), u1.y, a3);
        }
    }
    uint32_t* d = xcf + ((size_t)((r >> 7) * (DINNER >> 5) + (c4 >> 5))) * 2048;
    const int rr = r & 127, kk = c4 & 31;
    d[aidx16(rr, kk + 0)] = pack_h2(siluf(a0), siluf(a1));
    d[aidx16(rr, kk + 2)] = pack_h2(siluf(a2), siluf(a3));
}

// y = fp16((softplus(dproj)*bc + D) * xc * silu(z)), fragment-A layout
__global__ void __launch_bounds__(128)
combine_kernel(const __half* __restrict__ xz, const uint32_t* __restrict__ xcf,
               const float* __restrict__ proj, const float* __restrict__ D,
               uint32_t* __restrict__ yf)
{
    const int r   = blockIdx.x;
    const int tid = threadIdx.x;
    __shared__ float sbc;

    const float* prow = proj + (size_t)r * NPROJ;
    if (tid < 32) {
        float v = 0.f;
        if (tid < D_STATE) v = prow[tid] * prow[D_STATE + tid];
#pragma unroll
        for (int o = 8; o > 0; o >>= 1) v += __shfl_xor_sync(0xffffffffu, v, o);
        if (tid == 0) sbc = v;
    }
    __syncthreads();
    const float bc = sbc;

    const __half* zrow = xz + (size_t)r * NXZ + DINNER;
    const int rr = r & 127;
    const size_t rowbase = ((size_t)(r >> 7) * (DINNER >> 5)) * 2048;

#pragma unroll
    for (int i = 0; i < 4; i++) {
        const int c = (i * 128 + tid) * 4;
        const float4 dp = *reinterpret_cast<const float4*>(&prow[2 * D_STATE + c]);
        const __half2* zp = reinterpret_cast<const __half2*>(&zrow[c]);
        const float2 z0 = __half22float2(zp[0]);
        const float2 z1 = __half22float2(zp[1]);
        const float4 Dv = *reinterpret_cast<const float4*>(&D[c]);
        const size_t base = rowbase + (size_t)(c >> 5) * 2048;
        const int kk = c & 31;
        const int i0 = aidx16(rr, kk + 0);
        const int i1 = aidx16(rr, kk + 2);
        const __half2 h0 = *reinterpret_cast<const __half2*>(&xcf[base + i0]);
        const __half2 h1 = *reinterpret_cast<const __half2*>(&xcf[base + i1]);
        const float x0 = __low2float(h0),  x1 = __high2float(h0);
        const float x2 = __low2float(h1),  x3 = __high2float(h1);
        const float y0 = (softplusf(dp.x) * bc + Dv.x) * x0 * siluf(z0.x);
        const float y1 = (softplusf(dp.y) * bc + Dv.y) * x1 * siluf(z0.y);
        const float y2 = (softplusf(dp.z) * bc + Dv.z) * x2 * siluf(z1.x);
        const float y3 = (softplusf(dp.w) * bc + Dv.w) * x3 * siluf(z1.y);
        yf[base + i0] = pack_h2(y0, y1);
        yf[base + i1] = pack_h2(y2, y3);
    }
}

// ---------------------------------------------------------------------------
// Launch
// ---------------------------------------------------------------------------
extern "C" void kernel_launch(void* const* d_in, const int* in_sizes, int n_in,
                              void* d_out, int out_size)
{
    const float* x      = (const float*)d_in[0];
    const float* W_in   = (const float*)d_in[1];
    const float* conv_w = (const float*)d_in[2];
    const float* conv_b = (const float*)d_in[3];
    const float* W_xp   = (const float*)d_in[4];
    const float* D      = (const float*)d_in[5];
    const float* W_out  = (const float*)d_in[6];
    float* out = (float*)d_out;

    void *p_xz, *p_proj, *p_xf, *p_winf, *p_xcf, *p_wxpf, *p_yf, *p_woutf;
    cudaGetSymbolAddress(&p_xz,    g_xz);
    cudaGetSymbolAddress(&p_proj,  g_proj);
    cudaGetSymbolAddress(&p_xf,    g_xf);
    cudaGetSymbolAddress(&p_winf,  g_winf);
    cudaGetSymbolAddress(&p_xcf,   g_xcf);
    cudaGetSymbolAddress(&p_wxpf,  g_wxpf);
    cudaGetSymbolAddress(&p_yf,    g_yf);
    cudaGetSymbolAddress(&p_woutf, g_woutf);

    cudaFuncSetAttribute(gemm_f16<true>,  cudaFuncAttributeMaxDynamicSharedMemorySize, 65536);
    cudaFuncSetAttribute(gemm_f16<false>, cudaFuncAttributeMaxDynamicSharedMemorySize, 65536);

    // Prep: fp16-round + fragment-permute the GEMM operands
    prep_frag_a<<<(NROWS * (DMODEL / 4)) / 256, 256>>>(x, (uint32_t*)p_xf, NROWS, DMODEL);
    prep_frag_b<<<(NXZ * (DMODEL / 4)) / 256, 256>>>(W_in, (uint32_t*)p_winf, NXZ, DMODEL, NXZ);
    prep_frag_b<<<(NPROJ_PAD * (DINNER / 4)) / 256, 256>>>(W_xp, (uint32_t*)p_wxpf, NPROJ, DINNER, NPROJ_PAD);
    prep_frag_b<<<(DMODEL * (DINNER / 4)) / 256, 256>>>(W_out, (uint32_t*)p_woutf, DMODEL, DINNER, DMODEL);

    // GEMM1: xz = x @ W_in^T   (8192 x 4096 x 1024), fp16 output
    gemm_f16<true><<<dim3(NXZ / 128, NROWS / 128), 128, 65536>>>(
        (const uint32_t*)p_xf, (const uint32_t*)p_winf, p_xz,
        NROWS, NXZ, DMODEL / 32);

    // conv + SiLU -> xc (fp16 fragment layout)
    conv_silu_kernel<<<(NROWS * 512) / 256, 256>>>(
        (const __half*)p_xz, conv_w, conv_b, (uint32_t*)p_xcf);

    // GEMM2: proj = xc @ W_xproj^T  (8192 x 2080 x 2048), frag N padded to 2176
    gemm_f16<false><<<dim3(NPROJ_PAD / 128, NROWS / 128), 128, 65536>>>(
        (const uint32_t*)p_xcf, (const uint32_t*)p_wxpf, p_proj,
        NROWS, NPROJ, DINNER / 32);

    // combine -> y (fp16 fragment layout)
    combine_kernel<<<NROWS, 128>>>(
        (const __half*)p_xz, (const uint32_t*)p_xcf, (const float*)p_proj, D, (uint32_t*)p_yf);

    // GEMM3: out = y @ W_out^T   (8192 x 1024 x 2048), fp32 output
    gemm_f16<false><<<dim3(DMODEL / 128, NROWS / 128), 128, 65536>>>(
        (const uint32_t*)p_yf, (const uint32_t*)p_woutf, out,
        NROWS, DMODEL, DINNER / 32);
}

// round 13
// speedup vs baseline: 2.1579x; 1.1137x over previous
#include <cuda_runtime.h>
#include <cuda_fp16.h>
#include <cstdint>

// ---------------------------------------------------------------------------
// SelectiveSSM on GB300 (base sm_103 target => mma.sync path).
// R13 over passing R12 (607.3 us): all fragment-layout PRODUCERS (conv,
// combine, prep_a, prep_b) restructured so each thread computes exactly the
// 8 elements of one uint4 fragment slot -> every store is STG.128 and each
// warp writes 512B contiguous (kills the scatter-write sector explosion).
// GEMM kernels byte-identical to R12.
// ---------------------------------------------------------------------------

#define D_STATE 16
#define BSZ     2
#define LSEQ    4096
#define DMODEL  1024
#define DINNER  2048
#define NROWS   (BSZ * LSEQ)            // 8192
#define NXZ     (2 * DINNER)            // 4096
#define NPROJ   (2 * D_STATE + DINNER)  // 2080
#define NPROJ_PAD 2176                  // 17 * 128

// Scratch (device globals: allocation-free)
__device__ __half g_xz[NROWS * (size_t)NXZ];       // GEMM1 out (fp16, normal layout)
__device__ float  g_proj[NROWS * (size_t)NPROJ];   // GEMM2 out (fp32, normal layout)
// fragment-major fp16 operands (u32 = packed half2)
__device__ uint32_t g_xf[NROWS * (size_t)DMODEL / 2];        // x       (A, GEMM1)
__device__ uint32_t g_winf[NXZ * (size_t)DMODEL / 2];        // W_in    (B, GEMM1)
__device__ uint32_t g_xcf[NROWS * (size_t)DINNER / 2];       // xc      (A, GEMM2)
__device__ uint32_t g_wxpf[NPROJ_PAD * (size_t)DINNER / 2];  // W_xproj (B, GEMM2)
__device__ uint32_t g_yf[NROWS * (size_t)DINNER / 2];        // y       (A, GEMM3)
__device__ uint32_t g_woutf[DMODEL * (size_t)DINNER / 2];    // W_out   (B, GEMM3)

// ---------------------------------------------------------------------------
// fp16 fragment layout, per 128(row) x 32(k) tile = 2048 u32 (8 KB).
// A-slot (uint4) at (kstep_in, mtile, lane): holds
//   reg0=(r0, c0:c0+1) reg1=(r0+8, c0:c0+1) reg2=(r0, c0+8:c0+9) reg3=(r0+8, ...)
//   where r0 = mtile*16 + (lane>>2), c0 = kstep_in*16 + 2*(lane&3).
// B-slot (uint2) at (kstep_in, ntile, lane): holds
//   reg0=(n0, c0:c0+1) reg1=(n0, c0+8:c0+9), n0 = ntile*8 + (lane>>2).
// ---------------------------------------------------------------------------

__device__ __forceinline__ uint32_t pack_h2(float lo, float hi) {
    __half2 h = __floats2half2_rn(lo, hi);   // low 16 bits = first arg
    return *reinterpret_cast<uint32_t*>(&h);
}

__device__ __forceinline__ void mma16(float acc[4], const uint32_t a[4], const uint32_t b[2]) {
    asm volatile(
        "mma.sync.aligned.m16n8k16.row.col.f32.f16.f16.f32 "
        "{%0,%1,%2,%3}, {%4,%5,%6,%7}, {%8,%9}, {%0,%1,%2,%3};"
        : "+f"(acc[0]), "+f"(acc[1]), "+f"(acc[2]), "+f"(acc[3])
        : "r"(a[0]), "r"(a[1]), "r"(a[2]), "r"(a[3]), "r"(b[0]), "r"(b[1]));
}

#define CP_ASYNC16(dst_u32, src_ptr) \
    asm volatile("cp.async.cg.shared.global [%0], [%1], 16;" \
                 :: "r"(dst_u32), "l"(src_ptr) : "memory")
#define CP_COMMIT() asm volatile("cp.async.commit_group;" ::: "memory")
#define CP_WAIT0()  asm volatile("cp.async.wait_group 0;" ::: "memory")
#define CP_WAIT1()  asm volatile("cp.async.wait_group 1;" ::: "memory")
#define CP_WAIT2()  asm volatile("cp.async.wait_group 2;" ::: "memory")

__device__ __forceinline__ uint32_t smem_u32a(const void* p) {
    uint32_t a;
    asm("{ .reg .u64 t; cvta.to.shared.u64 t, %1; cvt.u32.u64 %0, t; }"
        : "=r"(a) : "l"(p));
    return a;
}

// ---------------------------------------------------------------------------
// fp16 GEMM (byte-identical to passing R12).
// CTA 128x128, BK=32, 128 threads, warp grid 2x2, warp tile 64x64.
// smem: 4 buffers x 16 KB = 64 KB dynamic. 2 CTA/SM. 4-stage pipeline.
// ---------------------------------------------------------------------------
template<bool HALF_OUT>
__global__ void __launch_bounds__(128, 2)
gemm_f16(const uint32_t* __restrict__ Af, const uint32_t* __restrict__ Bf,
         void* __restrict__ Cv, int M, int N, int KT /* = K/32 */)
{
    extern __shared__ uint32_t smem[];   // 4 x 4096 u32
    const int tid  = threadIdx.x;
    const int lane = tid & 31;
    const int warp = tid >> 5;
    const int wm   = warp >> 1;       // 0..1
    const int wn   = warp & 1;        // 0..1
    const int m0   = blockIdx.y * 128;
    const int n0   = blockIdx.x * 128;

    const uint32_t sb = smem_u32a(smem);
    const uint32_t* At = Af + (size_t)blockIdx.y * KT * 2048;
    const uint32_t* Bt = Bf + (size_t)blockIdx.x * KT * 2048;

    float acc[4][8][4];
#pragma unroll
    for (int i = 0; i < 4; i++)
#pragma unroll
        for (int j = 0; j < 8; j++)
#pragma unroll
            for (int q = 0; q < 4; q++) acc[i][j][q] = 0.f;

    // ---- prologue: stage tiles 0..2 into buffers 0..2 (stage-ahead 3)
#pragma unroll
    for (int p = 0; p < 3; p++) {
        if (p < KT) {
            const uint32_t boff = (uint32_t)p * 16384u;
            const uint32_t* An = At + (size_t)p * 2048;
            const uint32_t* Bn = Bt + (size_t)p * 2048;
#pragma unroll
            for (int i = 0; i < 4; i++) {
                const int s = tid + 128 * i;
                CP_ASYNC16(sb + boff + (uint32_t)s * 16,         An + (size_t)s * 4);
                CP_ASYNC16(sb + boff + 8192u + (uint32_t)s * 16, Bn + (size_t)s * 4);
            }
            CP_COMMIT();
        }
    }

    for (int kt = 0; kt < KT; ++kt) {
        const int remaining = KT - 1 - kt;
        if (remaining >= 2)      CP_WAIT2();
        else if (remaining == 1) CP_WAIT1();
        else                     CP_WAIT0();
        __syncthreads();

        if (kt + 3 < KT) {
            const uint32_t boff = (uint32_t)((kt + 3) & 3) * 16384u;
            const uint32_t* An = At + (size_t)(kt + 3) * 2048;
            const uint32_t* Bn = Bt + (size_t)(kt + 3) * 2048;
#pragma unroll
            for (int i = 0; i < 4; i++) {
                const int s = tid + 128 * i;
                CP_ASYNC16(sb + boff + (uint32_t)s * 16,         An + (size_t)s * 4);
                CP_ASYNC16(sb + boff + 8192u + (uint32_t)s * 16, Bn + (size_t)s * 4);
            }
            CP_COMMIT();
        }

        const uint32_t* Asb = smem + (kt & 3) * 4096;
        const uint32_t* Bsb = Asb + 2048;
#pragma unroll
        for (int ks = 0; ks < 2; ++ks) {
            uint32_t af[4][4];
            uint32_t bf[8][2];
#pragma unroll
            for (int im = 0; im < 4; ++im) {
                const int mt = wm * 4 + im;
                const uint4 t = *reinterpret_cast<const uint4*>(
                    &Asb[((((ks << 3) + mt) << 5) + lane) * 4]);
                af[im][0] = t.x; af[im][1] = t.y; af[im][2] = t.z; af[im][3] = t.w;
            }
#pragma unroll
            for (int jn = 0; jn < 8; ++jn) {
                const int nt = wn * 8 + jn;
                const uint2 t = *reinterpret_cast<const uint2*>(
                    &Bsb[((((ks << 4) + nt) << 5) + lane) * 2]);
                bf[jn][0] = t.x; bf[jn][1] = t.y;
            }
#pragma unroll
            for (int im = 0; im < 4; ++im)
#pragma unroll
                for (int jn = 0; jn < 8; ++jn)
                    mma16(acc[im][jn], af[im], bf[jn]);
        }
    }

    // ---- epilogue
    const int g = lane >> 2, t = lane & 3;
#pragma unroll
    for (int im = 0; im < 4; ++im) {
        const int mrow = m0 + wm * 64 + im * 16 + g;
#pragma unroll
        for (int jn = 0; jn < 8; ++jn) {
            const int nb = n0 + wn * 64 + jn * 8;
            if (nb < N) {
                if (HALF_OUT) {
                    __half* C = (__half*)Cv;
                    *reinterpret_cast<__half2*>(&C[(size_t)mrow * N + nb + 2 * t]) =
                        __floats2half2_rn(acc[im][jn][0], acc[im][jn][1]);
                    *reinterpret_cast<__half2*>(&C[(size_t)(mrow + 8) * N + nb + 2 * t]) =
                        __floats2half2_rn(acc[im][jn][2], acc[im][jn][3]);
                } else {
                    float* C = (float*)Cv;
                    float2 v0 = make_float2(acc[im][jn][0], acc[im][jn][1]);
                    float2 v1 = make_float2(acc[im][jn][2], acc[im][jn][3]);
                    *reinterpret_cast<float2*>(&C[(size_t)mrow * N + nb + 2 * t])       = v0;
                    *reinterpret_cast<float2*>(&C[(size_t)(mrow + 8) * N + nb + 2 * t]) = v1;
                }
            }
        }
    }
}

// ---------------------------------------------------------------------------
// Preps: slot-per-thread, coalesced STG.128 / STG.64
// ---------------------------------------------------------------------------
__global__ void __launch_bounds__(256)
prep_frag_a(const float* __restrict__ src, uint32_t* __restrict__ dst, int M, int K)
{
    const int w    = blockIdx.x * 8 + (threadIdx.x >> 5);
    const int lane = threadIdx.x & 31;
    const int TC   = K >> 5;
    const int tile = w >> 4;            // tr*TC + tc
    const int slab = w & 15;            // ksin*8 + mtile
    const int tr = tile / TC, tc = tile - tr * TC;
    const int ksin = slab >> 3, mtile = slab & 7;
    const int r0 = tr * 128 + mtile * 16 + (lane >> 2);
    const int c0 = tc * 32 + ksin * 16 + 2 * (lane & 3);

    const float2 v0 = *reinterpret_cast<const float2*>(&src[(size_t)r0 * K + c0]);
    const float2 v1 = *reinterpret_cast<const float2*>(&src[(size_t)(r0 + 8) * K + c0]);
    const float2 v2 = *reinterpret_cast<const float2*>(&src[(size_t)r0 * K + c0 + 8]);
    const float2 v3 = *reinterpret_cast<const float2*>(&src[(size_t)(r0 + 8) * K + c0 + 8]);
    uint4 o;
    o.x = pack_h2(v0.x, v0.y);
    o.y = pack_h2(v1.x, v1.y);
    o.z = pack_h2(v2.x, v2.y);
    o.w = pack_h2(v3.x, v3.y);
    *reinterpret_cast<uint4*>(dst + (size_t)tile * 2048 + slab * 128 + lane * 4) = o;
}

__global__ void __launch_bounds__(256)
prep_frag_b(const float* __restrict__ src, uint32_t* __restrict__ dst,
            int Nr, int K, int Npad)
{
    const int w    = blockIdx.x * 8 + (threadIdx.x >> 5);
    const int lane = threadIdx.x & 31;
    const int TC   = K >> 5;
    const int tile = w >> 5;            // tr*TC + tc
    const int slab = w & 31;            // ksin*16 + ntile
    const int tr = tile / TC, tc = tile - tr * TC;
    const int ksin = slab >> 4, ntile = slab & 15;
    const int n0 = tr * 128 + ntile * 8 + (lane >> 2);
    const int c0 = tc * 32 + ksin * 16 + 2 * (lane & 3);

    float2 v0 = make_float2(0.f, 0.f), v1 = make_float2(0.f, 0.f);
    if (n0 < Nr) {
        v0 = *reinterpret_cast<const float2*>(&src[(size_t)n0 * K + c0]);
        v1 = *reinterpret_cast<const float2*>(&src[(size_t)n0 * K + c0 + 8]);
    }
    uint2 o;
    o.x = pack_h2(v0.x, v0.y);
    o.y = pack_h2(v1.x, v1.y);
    *reinterpret_cast<uint2*>(dst + (size_t)tile * 2048 + slab * 64 + lane * 2) = o;
}

// ---------------------------------------------------------------------------
// Elementwise: slot-per-thread producers
// ---------------------------------------------------------------------------
__device__ __forceinline__ float siluf(float v)     { return v / (1.f + expf(-v)); }
__device__ __forceinline__ float softplusf(float v) { return fmaxf(v, 0.f) + log1pf(expf(-fabsf(v))); }

// conv+silu for channel pair (c, c+1) at token row -> packed fp16 pair
__device__ __forceinline__ uint32_t conv_pair(
    const __half* __restrict__ xz, const float* __restrict__ cw,
    const float* __restrict__ cb, int row, int c)
{
    float a = cb[c], b = cb[c + 1];
    const int l = row & (LSEQ - 1);
#pragma unroll
    for (int k = 0; k < 4; k++) {
        if (l + k - 3 >= 0) {
            const float2 f = __half22float2(
                *reinterpret_cast<const __half2*>(&xz[(size_t)(row + k - 3) * NXZ + c]));
            a = fmaf(cw[c * 4 + k],       f.x, a);
            b = fmaf(cw[(c + 1) * 4 + k], f.y, b);
        }
    }
    return pack_h2(siluf(a), siluf(b));
}

// xc = fp16(silu(conv(xb))), fragment-A layout; one uint4 slot per thread.
// warps = 64 tiles * 128 ksteps * 8 mtiles = 65536 -> 8192 blocks.
__global__ void __launch_bounds__(256)
conv_silu_kernel(const __half* __restrict__ xz, const float* __restrict__ cw,
                 const float* __restrict__ cb, uint32_t* __restrict__ xcf)
{
    const int w    = blockIdx.x * 8 + (threadIdx.x >> 5);
    const int lane = threadIdx.x & 31;
    const int tile  = w >> 10;          // token-tile (128 rows)
    const int kstep = (w >> 3) & 127;   // 16-channel step
    const int mtile = w & 7;
    const int r0 = tile * 128 + mtile * 16 + (lane >> 2);
    const int c0 = kstep * 16 + 2 * (lane & 3);

    uint4 o;
    o.x = conv_pair(xz, cw, cb, r0,     c0);
    o.y = conv_pair(xz, cw, cb, r0 + 8, c0);
    o.z = conv_pair(xz, cw, cb, r0,     c0 + 8);
    o.w = conv_pair(xz, cw, cb, r0 + 8, c0 + 8);

    uint32_t* d = xcf + (size_t)(tile * (DINNER >> 5) + (kstep >> 1)) * 2048
                      + (((kstep & 1) * 8 + mtile) * 32 + lane) * 4;
    *reinterpret_cast<uint4*>(d) = o;
}

// combine for channel pair (c, c+1) at token row
__device__ __forceinline__ uint32_t comb_pair(
    const __half* __restrict__ xz, const float* __restrict__ proj,
    const float* __restrict__ D, int row, int c, float bc, uint32_t xc2)
{
    const float2 dp = *reinterpret_cast<const float2*>(&proj[(size_t)row * NPROJ + 2 * D_STATE + c]);
    const float2 z  = __half22float2(
        *reinterpret_cast<const __half2*>(&xz[(size_t)row * NXZ + DINNER + c]));
    const float2 Dv = *reinterpret_cast<const float2*>(&D[c]);
    const __half2 xh = *reinterpret_cast<const __half2*>(&xc2);
    const float y0 = (softplusf(dp.x) * bc + Dv.x) * __low2float(xh)  * siluf(z.x);
    const float y1 = (softplusf(dp.y) * bc + Dv.y) * __high2float(xh) * siluf(z.y);
    return pack_h2(y0, y1);
}

// y = fp16((softplus(dproj)*bc + D)*xc*silu(z)), fragment-A layout.
// grid = 64 token-tiles x 16 kstep-groups = 1024 blocks of 256.
__global__ void __launch_bounds__(256)
combine_kernel(const __half* __restrict__ xz, const uint32_t* __restrict__ xcf,
               const float* __restrict__ proj, const float* __restrict__ D,
               uint32_t* __restrict__ yf)
{
    __shared__ float sbc[128];
    const int tile = blockIdx.x >> 4;
    const int kgrp = blockIdx.x & 15;
    const int tid  = threadIdx.x;

    if (tid < 128) {
        const float* pr = proj + (size_t)(tile * 128 + tid) * NPROJ;
        float v = 0.f;
#pragma unroll
        for (int s = 0; s < D_STATE; s++) v = fmaf(pr[s], pr[D_STATE + s], v);
        sbc[tid] = v;
    }
    __syncthreads();

    const int warp = tid >> 5, lane = tid & 31;
#pragma unroll
    for (int i = 0; i < 8; i++) {
        const int slab  = warp * 8 + i;            // 0..63
        const int ks    = kgrp * 8 + (slab >> 3);  // global kstep 0..127
        const int mtile = slab & 7;
        const int rr0   = mtile * 16 + (lane >> 2);
        const int r0    = tile * 128 + rr0;
        const int c0    = ks * 16 + 2 * (lane & 3);
        const size_t base = (size_t)(tile * (DINNER >> 5) + (ks >> 1)) * 2048
                          + (((ks & 1) * 8 + mtile) * 32 + lane) * 4;
        const uint4 xin = *reinterpret_cast<const uint4*>(xcf + base);
        const float bc0 = sbc[rr0], bc1 = sbc[rr0 + 8];
        uint4 o;
        o.x = comb_pair(xz, proj, D, r0,     c0,     bc0, xin.x);
        o.y = comb_pair(xz, proj, D, r0 + 8, c0,     bc1, xin.y);
        o.z = comb_pair(xz, proj, D, r0,     c0 + 8, bc0, xin.z);
        o.w = comb_pair(xz, proj, D, r0 + 8, c0 + 8, bc1, xin.w);
        *reinterpret_cast<uint4*>(yf + base) = o;
    }
}

// ---------------------------------------------------------------------------
// Launch
// ---------------------------------------------------------------------------
extern "C" void kernel_launch(void* const* d_in, const int* in_sizes, int n_in,
                              void* d_out, int out_size)
{
    const float* x      = (const float*)d_in[0];
    const float* W_in   = (const float*)d_in[1];
    const float* conv_w = (const float*)d_in[2];
    const float* conv_b = (const float*)d_in[3];
    const float* W_xp   = (const float*)d_in[4];
    const float* D      = (const float*)d_in[5];
    const float* W_out  = (const float*)d_in[6];
    float* out = (float*)d_out;

    void *p_xz, *p_proj, *p_xf, *p_winf, *p_xcf, *p_wxpf, *p_yf, *p_woutf;
    cudaGetSymbolAddress(&p_xz,    g_xz);
    cudaGetSymbolAddress(&p_proj,  g_proj);
    cudaGetSymbolAddress(&p_xf,    g_xf);
    cudaGetSymbolAddress(&p_winf,  g_winf);
    cudaGetSymbolAddress(&p_xcf,   g_xcf);
    cudaGetSymbolAddress(&p_wxpf,  g_wxpf);
    cudaGetSymbolAddress(&p_yf,    g_yf);
    cudaGetSymbolAddress(&p_woutf, g_woutf);

    cudaFuncSetAttribute(gemm_f16<true>,  cudaFuncAttributeMaxDynamicSharedMemorySize, 65536);
    cudaFuncSetAttribute(gemm_f16<false>, cudaFuncAttributeMaxDynamicSharedMemorySize, 65536);

    // Preps: slot-per-thread fragment permute
    // prep_a(x): warps = (8192/128)*(1024/32)*16 = 32768 -> 4096 blocks
    prep_frag_a<<<4096, 256>>>(x, (uint32_t*)p_xf, NROWS, DMODEL);
    // prep_b(W_in): warps = (4096/128)*(1024/32)*32 = 32768 -> 4096 blocks
    prep_frag_b<<<4096, 256>>>(W_in, (uint32_t*)p_winf, NXZ, DMODEL, NXZ);
    // prep_b(W_xp): warps = (2176/128)*(2048/32)*32 = 34816 -> 4352 blocks
    prep_frag_b<<<4352, 256>>>(W_xp, (uint32_t*)p_wxpf, NPROJ, DINNER, NPROJ_PAD);
    // prep_b(W_out): warps = (1024/128)*(2048/32)*32 = 16384 -> 2048 blocks
    prep_frag_b<<<2048, 256>>>(W_out, (uint32_t*)p_woutf, DMODEL, DINNER, DMODEL);

    // GEMM1: xz = x @ W_in^T   (8192 x 4096 x 1024), fp16 output
    gemm_f16<true><<<dim3(NXZ / 128, NROWS / 128), 128, 65536>>>(
        (const uint32_t*)p_xf, (const uint32_t*)p_winf, p_xz,
        NROWS, NXZ, DMODEL / 32);

    // conv + SiLU -> xc (fragment layout): 65536 warps -> 8192 blocks
    conv_silu_kernel<<<8192, 256>>>(
        (const __half*)p_xz, conv_w, conv_b, (uint32_t*)p_xcf);

    // GEMM2: proj = xc @ W_xproj^T  (8192 x 2080 x 2048), frag N padded to 2176
    gemm_f16<false><<<dim3(NPROJ_PAD / 128, NROWS / 128), 128, 65536>>>(
        (const uint32_t*)p_xcf, (const uint32_t*)p_wxpf, p_proj,
        NROWS, NPROJ, DINNER / 32);

    // combine -> y (fragment layout): 64 tiles x 16 kgroups = 1024 blocks
    combine_kernel<<<1024, 256>>>(
        (const __half*)p_xz, (const uint32_t*)p_xcf, (const float*)p_proj, D,
        (uint32_t*)p_yf);

    // GEMM3: out = y @ W_out^T   (8192 x 1024 x 2048), fp32 output
    gemm_f16<false><<<dim3(DMODEL / 128, NROWS / 128), 128, 65536>>>(
        (const uint32_t*)p_yf, (const uint32_t*)p_woutf, out,
        NROWS, DMODEL, DINNER / 32);
}